// round 1
// baseline (speedup 1.0000x reference)
#include <cuda_runtime.h>
#include <math.h>

// Problem constants (shapes fixed by setup_inputs)
#define NV    4096          // batch per view
#define TWON  8192          // 2N rows total
#define FD    512           // feature dim
#define PD    128           // projection dim
#define INV_T 10.0f         // 1 / temperature (0.1)
#define BN_EPS  1e-5f
#define COS_EPS 1e-8f

// Scratch (no allocations allowed -> __device__ globals)
__device__ float g_h[TWON * PD];      // projected pre-BN activations
__device__ float g_zn[TWON * PD];     // row-normalized BN outputs
__device__ float g_sum[2 * PD];       // per-view per-col sum
__device__ float g_sumsq[2 * PD];     // per-view per-col sum of squares
__device__ float g_rowsum[TWON];      // sum_j S_ij (diag excluded)
__device__ float g_pos[TWON];         // S_{i, i^NV}

// ---------------------------------------------------------------------------
// K0: zero the accumulators (d_out is poisoned; scratch must be reset per call)
// ---------------------------------------------------------------------------
__global__ void k_zero() {
    int i = blockIdx.x * 256 + threadIdx.x;
    if (i < TWON) g_rowsum[i] = 0.0f;
    if (i < 2 * PD) { g_sum[i] = 0.0f; g_sumsq[i] = 0.0f; }
}

// ---------------------------------------------------------------------------
// K1: h = concat(x, xt) @ W + b    [8192 x 512] @ [512 x 128]
// 64x64 tile per block, BK=64, 256 threads, 4x4 micro-tile.
// Shared tiles stored k-major ([k][m] / [k][n]) for conflict-free fragment reads.
// ---------------------------------------------------------------------------
__global__ __launch_bounds__(256) void k_proj(const float* __restrict__ x,
                                              const float* __restrict__ xt,
                                              const float* __restrict__ W,
                                              const float* __restrict__ bias) {
    __shared__ float As[64][64];   // [k][m]
    __shared__ float Bs[64][64];   // [k][n]
    int tid = threadIdx.x;
    int tx = tid & 15, ty = tid >> 4;
    int m0 = blockIdx.y * 64;
    int n0 = blockIdx.x * 64;

    float acc[4][4] = {};

    for (int k0 = 0; k0 < FD; k0 += 64) {
        // Load A tile (transpose into [k][m])
        #pragma unroll
        for (int f = 0; f < 4; f++) {
            int idx = f * 256 + tid;
            int m  = idx >> 4;       // 0..63
            int k4 = idx & 15;       // 0..15
            int row = m0 + m;
            const float* src = (row < NV) ? (x + (size_t)row * FD)
                                          : (xt + (size_t)(row - NV) * FD);
            float4 v = *(const float4*)(src + k0 + k4 * 4);
            As[k4 * 4 + 0][m] = v.x;
            As[k4 * 4 + 1][m] = v.y;
            As[k4 * 4 + 2][m] = v.z;
            As[k4 * 4 + 3][m] = v.w;
        }
        // Load B tile (W already k-major: [FD][PD])
        #pragma unroll
        for (int f = 0; f < 4; f++) {
            int idx = f * 256 + tid;
            int k  = idx >> 4;       // 0..63
            int n4 = idx & 15;       // 0..15
            float4 v = *(const float4*)(W + (size_t)(k0 + k) * PD + n0 + n4 * 4);
            *(float4*)&Bs[k][n4 * 4] = v;
        }
        __syncthreads();

        #pragma unroll 8
        for (int k = 0; k < 64; k++) {
            float4 a = *(float4*)&As[k][ty * 4];
            float4 b = *(float4*)&Bs[k][tx * 4];
            float ar[4] = {a.x, a.y, a.z, a.w};
            float br[4] = {b.x, b.y, b.z, b.w};
            #pragma unroll
            for (int r = 0; r < 4; r++)
                #pragma unroll
                for (int c = 0; c < 4; c++)
                    acc[r][c] = fmaf(ar[r], br[c], acc[r][c]);
        }
        __syncthreads();
    }

    #pragma unroll
    for (int r = 0; r < 4; r++) {
        int row = m0 + ty * 4 + r;
        #pragma unroll
        for (int c = 0; c < 4; c++) {
            int col = n0 + tx * 4 + c;
            g_h[(size_t)row * PD + col] = acc[r][c] + bias[col];
        }
    }
}

// ---------------------------------------------------------------------------
// K2a: per-view column sums / sums of squares (for batch-stat BN)
// grid = 2 views * 32 row-chunks, 128 threads = one column each (coalesced)
// ---------------------------------------------------------------------------
__global__ void k_stats() {
    int c = threadIdx.x;             // 0..127
    int v = blockIdx.x >> 5;         // 0..1
    int chunk = blockIdx.x & 31;
    int r0 = v * NV + chunk * 128;
    float s = 0.0f, sq = 0.0f;
    for (int r = 0; r < 128; r++) {
        float h = g_h[(size_t)(r0 + r) * PD + c];
        s += h;
        sq += h * h;
    }
    atomicAdd(&g_sum[v * PD + c], s);
    atomicAdd(&g_sumsq[v * PD + c], sq);
}

// ---------------------------------------------------------------------------
// K2b: BN-normalize (batch stats), affine, then cosine row-normalize.
// One block (128 threads) per row.
// ---------------------------------------------------------------------------
__global__ void k_norm(const float* __restrict__ gamma,
                       const float* __restrict__ beta) {
    __shared__ float red[4];
    int c = threadIdx.x;
    int row = blockIdx.x;
    int v = row >> 12;               // /4096

    float mu   = g_sum[v * PD + c]   * (1.0f / NV);
    float var  = g_sumsq[v * PD + c] * (1.0f / NV) - mu * mu;
    float rstd = rsqrtf(var + BN_EPS);
    float z = gamma[c] * (g_h[(size_t)row * PD + c] - mu) * rstd + beta[c];

    float sq = z * z;
    #pragma unroll
    for (int o = 16; o > 0; o >>= 1)
        sq += __shfl_xor_sync(0xffffffffu, sq, o);
    if ((c & 31) == 0) red[c >> 5] = sq;
    __syncthreads();
    float tot = red[0] + red[1] + red[2] + red[3];
    float inv = 1.0f / fmaxf(sqrtf(tot), COS_EPS);
    g_zn[(size_t)row * PD + c] = z * inv;
}

// ---------------------------------------------------------------------------
// K3: fused similarity: for a 128x128 tile of sim = zn @ zn^T,
// compute exp(sim/T), skip diagonal, capture positive pair, reduce row-sums.
// 256 threads (16x16), 8x8 micro-tile, BK=32 (full K=128 in 4 chunks).
// Pure L2-resident operands (zn = 4 MB). FMA-pipe-bound.
// ---------------------------------------------------------------------------
__global__ __launch_bounds__(256, 2) void k_sim() {
    __shared__ float As[32][128];    // [k][i]
    __shared__ float Bs[32][128];    // [k][j]
    int tid = threadIdx.x;
    int tx = tid & 15, ty = tid >> 4;
    int i0 = blockIdx.y * 128;
    int j0 = blockIdx.x * 128;

    float acc[8][8] = {};

    for (int k0 = 0; k0 < PD; k0 += 32) {
        #pragma unroll
        for (int f = 0; f < 4; f++) {
            int idx = f * 256 + tid;
            int m  = idx >> 3;       // 0..127
            int k4 = idx & 7;        // 0..7
            float4 va = *(const float4*)(g_zn + (size_t)(i0 + m) * PD + k0 + k4 * 4);
            As[k4 * 4 + 0][m] = va.x;
            As[k4 * 4 + 1][m] = va.y;
            As[k4 * 4 + 2][m] = va.z;
            As[k4 * 4 + 3][m] = va.w;
            float4 vb = *(const float4*)(g_zn + (size_t)(j0 + m) * PD + k0 + k4 * 4);
            Bs[k4 * 4 + 0][m] = vb.x;
            Bs[k4 * 4 + 1][m] = vb.y;
            Bs[k4 * 4 + 2][m] = vb.z;
            Bs[k4 * 4 + 3][m] = vb.w;
        }
        __syncthreads();

        #pragma unroll 4
        for (int k = 0; k < 32; k++) {
            float4 a0 = *(float4*)&As[k][ty * 8];
            float4 a1 = *(float4*)&As[k][ty * 8 + 4];
            float4 b0 = *(float4*)&Bs[k][tx * 8];
            float4 b1 = *(float4*)&Bs[k][tx * 8 + 4];
            float ar[8] = {a0.x, a0.y, a0.z, a0.w, a1.x, a1.y, a1.z, a1.w};
            float br[8] = {b0.x, b0.y, b0.z, b0.w, b1.x, b1.y, b1.z, b1.w};
            #pragma unroll
            for (int r = 0; r < 8; r++)
                #pragma unroll
                for (int c = 0; c < 8; c++)
                    acc[r][c] = fmaf(ar[r], br[c], acc[r][c]);
        }
        __syncthreads();
    }

    // Epilogue: exp, diag skip, positive-pair capture, per-thread row partials
    float rowpart[8];
    #pragma unroll
    for (int r = 0; r < 8; r++) {
        int i = i0 + ty * 8 + r;
        int partner = i ^ NV;        // (i+N) mod 2N since 2N = 2*NV power of two
        float s = 0.0f;
        #pragma unroll
        for (int c = 0; c < 8; c++) {
            int j = j0 + tx * 8 + c;
            float val = (i == j) ? 0.0f : __expf(acc[r][c] * INV_T);
            if (j == partner) g_pos[i] = val;   // unique writer per i
            s += val;
        }
        rowpart[r] = s;
    }

    // Reduce the 16 tx-partials per row in smem (reuse As), one atomic per row
    float* red = &As[0][0];          // 128*17 = 2176 floats <= 4096 available
    #pragma unroll
    for (int r = 0; r < 8; r++)
        red[(ty * 8 + r) * 17 + tx] = rowpart[r];
    __syncthreads();
    if (tid < 128) {
        float s = 0.0f;
        #pragma unroll
        for (int t = 0; t < 16; t++) s += red[tid * 17 + t];
        atomicAdd(&g_rowsum[i0 + tid], s);
    }
}

// ---------------------------------------------------------------------------
// K4: V_i = -log(pos_i / rowsum_i) = log(rowsum_i) - log(pos_i)
// ---------------------------------------------------------------------------
__global__ void k_final(float* __restrict__ out) {
    int i = blockIdx.x * 256 + threadIdx.x;
    if (i < TWON) out[i] = logf(g_rowsum[i]) - logf(g_pos[i]);
}

// ---------------------------------------------------------------------------
extern "C" void kernel_launch(void* const* d_in, const int* in_sizes, int n_in,
                              void* d_out, int out_size) {
    const float* x     = (const float*)d_in[0];
    const float* xt    = (const float*)d_in[1];
    const float* W     = (const float*)d_in[2];
    const float* bias  = (const float*)d_in[3];
    const float* gamma = (const float*)d_in[4];
    const float* beta  = (const float*)d_in[5];
    float* out = (float*)d_out;

    k_zero <<<32, 256>>>();
    k_proj <<<dim3(PD / 64, TWON / 64), 256>>>(x, xt, W, bias);
    k_stats<<<64, 128>>>();
    k_norm <<<TWON, 128>>>(gamma, beta);
    k_sim  <<<dim3(TWON / 128, TWON / 128), 256>>>();
    k_final<<<32, 256>>>(out);
}

// round 4
// speedup vs baseline: 2.3164x; 2.3164x over previous
#include <cuda_runtime.h>
#include <math.h>
#include <cstdint>

// Problem constants (shapes fixed by setup_inputs)
#define NV    4096          // batch per view
#define TWON  8192          // 2N rows total
#define FD    512           // feature dim
#define PD    128           // projection dim
#define INV_T 10.0f         // 1 / temperature (0.1)
#define BN_EPS  1e-5f
#define COS_EPS 1e-8f

// Scratch (no allocations allowed -> __device__ globals)
__device__ float g_h[TWON * PD];      // projected pre-BN activations
__device__ float g_zn[TWON * PD];     // row-normalized BN outputs (tf32-rounded)
__device__ float g_sum[2 * PD];       // per-view per-col sum
__device__ float g_sumsq[2 * PD];     // per-view per-col sum of squares
__device__ float g_rowsum[TWON];      // sum_j S_ij (diag excluded)
__device__ float g_pos[TWON];         // S_{i, i^NV}

// RNA-rounded tf32 (unbiased; avoids truncation bias amplified by exp(10*sim))
__device__ __forceinline__ float to_tf32(float x) {
    uint32_t u;
    asm("cvt.rna.tf32.f32 %0, %1;" : "=r"(u) : "f"(x));
    return __uint_as_float(u);
}

// ---------------------------------------------------------------------------
// K0: zero accumulators
// ---------------------------------------------------------------------------
__global__ void k_zero() {
    int i = blockIdx.x * 256 + threadIdx.x;
    if (i < TWON) g_rowsum[i] = 0.0f;
    if (i < 2 * PD) { g_sum[i] = 0.0f; g_sumsq[i] = 0.0f; }
}

// ---------------------------------------------------------------------------
// K1: h = concat(x, xt) @ W + b    [8192 x 512] @ [512 x 128]
// ---------------------------------------------------------------------------
__global__ __launch_bounds__(256) void k_proj(const float* __restrict__ x,
                                              const float* __restrict__ xt,
                                              const float* __restrict__ W,
                                              const float* __restrict__ bias) {
    __shared__ float As[64][64];   // [k][m]
    __shared__ float Bs[64][64];   // [k][n]
    int tid = threadIdx.x;
    int tx = tid & 15, ty = tid >> 4;
    int m0 = blockIdx.y * 64;
    int n0 = blockIdx.x * 64;

    float acc[4][4] = {};

    for (int k0 = 0; k0 < FD; k0 += 64) {
        #pragma unroll
        for (int f = 0; f < 4; f++) {
            int idx = f * 256 + tid;
            int m  = idx >> 4;
            int k4 = idx & 15;
            int row = m0 + m;
            const float* src = (row < NV) ? (x + (size_t)row * FD)
                                          : (xt + (size_t)(row - NV) * FD);
            float4 v = *(const float4*)(src + k0 + k4 * 4);
            As[k4 * 4 + 0][m] = v.x;
            As[k4 * 4 + 1][m] = v.y;
            As[k4 * 4 + 2][m] = v.z;
            As[k4 * 4 + 3][m] = v.w;
        }
        #pragma unroll
        for (int f = 0; f < 4; f++) {
            int idx = f * 256 + tid;
            int k  = idx >> 4;
            int n4 = idx & 15;
            float4 v = *(const float4*)(W + (size_t)(k0 + k) * PD + n0 + n4 * 4);
            *(float4*)&Bs[k][n4 * 4] = v;
        }
        __syncthreads();

        #pragma unroll 8
        for (int k = 0; k < 64; k++) {
            float4 a = *(float4*)&As[k][ty * 4];
            float4 b = *(float4*)&Bs[k][tx * 4];
            float ar[4] = {a.x, a.y, a.z, a.w};
            float br[4] = {b.x, b.y, b.z, b.w};
            #pragma unroll
            for (int r = 0; r < 4; r++)
                #pragma unroll
                for (int c = 0; c < 4; c++)
                    acc[r][c] = fmaf(ar[r], br[c], acc[r][c]);
        }
        __syncthreads();
    }

    #pragma unroll
    for (int r = 0; r < 4; r++) {
        int row = m0 + ty * 4 + r;
        #pragma unroll
        for (int c = 0; c < 4; c++) {
            int col = n0 + tx * 4 + c;
            g_h[(size_t)row * PD + col] = acc[r][c] + bias[col];
        }
    }
}

// ---------------------------------------------------------------------------
// K2a: per-view column sums / sums of squares
// ---------------------------------------------------------------------------
__global__ void k_stats() {
    int c = threadIdx.x;
    int v = blockIdx.x >> 5;
    int chunk = blockIdx.x & 31;
    int r0 = v * NV + chunk * 128;
    float s = 0.0f, sq = 0.0f;
    for (int r = 0; r < 128; r++) {
        float h = g_h[(size_t)(r0 + r) * PD + c];
        s += h;
        sq += h * h;
    }
    atomicAdd(&g_sum[v * PD + c], s);
    atomicAdd(&g_sumsq[v * PD + c], sq);
}

// ---------------------------------------------------------------------------
// K2b: BN-normalize + cosine row-normalize; emit tf32-rounded zn
// ---------------------------------------------------------------------------
__global__ void k_norm(const float* __restrict__ gamma,
                       const float* __restrict__ beta) {
    __shared__ float red[4];
    int c = threadIdx.x;
    int row = blockIdx.x;
    int v = row >> 12;

    float mu   = g_sum[v * PD + c]   * (1.0f / NV);
    float var  = g_sumsq[v * PD + c] * (1.0f / NV) - mu * mu;
    float rstd = rsqrtf(var + BN_EPS);
    float z = gamma[c] * (g_h[(size_t)row * PD + c] - mu) * rstd + beta[c];

    float sq = z * z;
    #pragma unroll
    for (int o = 16; o > 0; o >>= 1)
        sq += __shfl_xor_sync(0xffffffffu, sq, o);
    if ((c & 31) == 0) red[c >> 5] = sq;
    __syncthreads();
    float tot = red[0] + red[1] + red[2] + red[3];
    float inv = 1.0f / fmaxf(sqrtf(tot), COS_EPS);
    g_zn[(size_t)row * PD + c] = to_tf32(z * inv);
}

// ---------------------------------------------------------------------------
// K3: fused sim via mma.sync tf32 (m16n8k8). 128x128 tile per 256-thread CTA.
// 8 warps in 4x2 grid; warp tile 32x64 = 2x8 mma grid. K=128 in 16 steps.
// SMEM: A,B tiles 128 x (128+4 pad) fp32 -> all fragment LDS conflict-free.
// Epilogue fused: exp, diag-zero, positive-pair capture, row-sum atomics.
// ---------------------------------------------------------------------------
#define SPAD 132
#define SIM_SMEM_BYTES (2 * 128 * SPAD * 4)

__global__ __launch_bounds__(256, 1) void k_sim_mma() {
    extern __shared__ float sm[];
    float* As = sm;                   // [128][SPAD]
    float* Bs = sm + 128 * SPAD;      // [128][SPAD]
    int tid = threadIdx.x;
    int lane = tid & 31, wid = tid >> 5;
    int i0 = blockIdx.y * 128;
    int j0 = blockIdx.x * 128;

    // Load tiles (rows already tf32-rounded in g_zn)
    #pragma unroll
    for (int f = 0; f < 16; f++) {
        int idx = f * 256 + tid;      // 4096 float4 slots
        int m  = idx >> 5;            // 0..127
        int c4 = idx & 31;            // 0..31
        float4 va = *(const float4*)(g_zn + (size_t)(i0 + m) * PD + c4 * 4);
        *(float4*)(As + m * SPAD + c4 * 4) = va;
        float4 vb = *(const float4*)(g_zn + (size_t)(j0 + m) * PD + c4 * 4);
        *(float4*)(Bs + m * SPAD + c4 * 4) = vb;
    }
    __syncthreads();

    int g = lane >> 2, tig = lane & 3;
    int rm = (wid & 3) * 32;          // warp row base (i-local)
    int cn = (wid >> 2) * 64;         // warp col base (j-local)

    float acc[2][8][4] = {};
    const float* Arow = As + (rm + g) * SPAD + tig;
    const float* Brow = Bs + (cn + g) * SPAD + tig;

    #pragma unroll
    for (int k0 = 0; k0 < 128; k0 += 8) {
        uint32_t a[2][4];
        #pragma unroll
        for (int mt = 0; mt < 2; mt++) {
            const float* p = Arow + mt * 16 * SPAD + k0;
            a[mt][0] = __float_as_uint(p[0]);
            a[mt][1] = __float_as_uint(p[8 * SPAD]);
            a[mt][2] = __float_as_uint(p[4]);
            a[mt][3] = __float_as_uint(p[8 * SPAD + 4]);
        }
        #pragma unroll
        for (int nt = 0; nt < 8; nt++) {
            const float* q = Brow + nt * 8 * SPAD + k0;
            uint32_t b0 = __float_as_uint(q[0]);
            uint32_t b1 = __float_as_uint(q[4]);
            #pragma unroll
            for (int mt = 0; mt < 2; mt++) {
                asm volatile(
                    "mma.sync.aligned.m16n8k8.row.col.f32.tf32.tf32.f32 "
                    "{%0,%1,%2,%3}, {%4,%5,%6,%7}, {%8,%9}, {%0,%1,%2,%3};"
                    : "+f"(acc[mt][nt][0]), "+f"(acc[mt][nt][1]),
                      "+f"(acc[mt][nt][2]), "+f"(acc[mt][nt][3])
                    : "r"(a[mt][0]), "r"(a[mt][1]), "r"(a[mt][2]), "r"(a[mt][3]),
                      "r"(b0), "r"(b1));
            }
        }
    }

    // Epilogue: fragment (mt,nt) reg c -> rows r0=g / r1=g+8, cols tig*2+{0,1}
    #pragma unroll
    for (int mt = 0; mt < 2; mt++) {
        int r0 = i0 + rm + mt * 16 + g;
        int r1 = r0 + 8;
        int p0 = r0 ^ NV;             // positive-pair column for row r0
        int p1 = r1 ^ NV;
        float s0 = 0.0f, s1 = 0.0f;
        #pragma unroll
        for (int nt = 0; nt < 8; nt++) {
            int jc = j0 + cn + nt * 8 + tig * 2;
            float v0 = (r0 == jc    ) ? 0.0f : __expf(acc[mt][nt][0] * INV_T);
            float v1 = (r0 == jc + 1) ? 0.0f : __expf(acc[mt][nt][1] * INV_T);
            float v2 = (r1 == jc    ) ? 0.0f : __expf(acc[mt][nt][2] * INV_T);
            float v3 = (r1 == jc + 1) ? 0.0f : __expf(acc[mt][nt][3] * INV_T);
            if (jc     == p0) g_pos[r0] = v0;
            if (jc + 1 == p0) g_pos[r0] = v1;
            if (jc     == p1) g_pos[r1] = v2;
            if (jc + 1 == p1) g_pos[r1] = v3;
            s0 += v0 + v1;
            s1 += v2 + v3;
        }
        // reduce across the 4 lanes of the quad (same g, tig 0..3)
        s0 += __shfl_xor_sync(0xffffffffu, s0, 1);
        s0 += __shfl_xor_sync(0xffffffffu, s0, 2);
        s1 += __shfl_xor_sync(0xffffffffu, s1, 1);
        s1 += __shfl_xor_sync(0xffffffffu, s1, 2);
        if (tig == 0) {
            atomicAdd(&g_rowsum[r0], s0);
            atomicAdd(&g_rowsum[r1], s1);
        }
    }
}

// ---------------------------------------------------------------------------
// K4: V_i = log(rowsum_i) - log(pos_i)
// ---------------------------------------------------------------------------
__global__ void k_final(float* __restrict__ out) {
    int i = blockIdx.x * 256 + threadIdx.x;
    if (i < TWON) out[i] = logf(g_rowsum[i]) - logf(g_pos[i]);
}

// ---------------------------------------------------------------------------
extern "C" void kernel_launch(void* const* d_in, const int* in_sizes, int n_in,
                              void* d_out, int out_size) {
    const float* x     = (const float*)d_in[0];
    const float* xt    = (const float*)d_in[1];
    const float* W     = (const float*)d_in[2];
    const float* bias  = (const float*)d_in[3];
    const float* gamma = (const float*)d_in[4];
    const float* beta  = (const float*)d_in[5];
    float* out = (float*)d_out;

    cudaFuncSetAttribute(k_sim_mma, cudaFuncAttributeMaxDynamicSharedMemorySize,
                         SIM_SMEM_BYTES);

    k_zero <<<32, 256>>>();
    k_proj <<<dim3(PD / 64, TWON / 64), 256>>>(x, xt, W, bias);
    k_stats<<<64, 128>>>();
    k_norm <<<TWON, 128>>>(gamma, beta);
    k_sim_mma<<<dim3(TWON / 128, TWON / 128), 256, SIM_SMEM_BYTES>>>();
    k_final<<<32, 256>>>(out);
}

// round 5
// speedup vs baseline: 3.6851x; 1.5909x over previous
#include <cuda_runtime.h>
#include <cuda_bf16.h>
#include <math.h>
#include <cstdint>

// Problem constants (shapes fixed by setup_inputs)
#define NV    4096          // batch per view
#define TWON  8192          // 2N rows total
#define FD    512           // feature dim
#define PD    128           // projection dim
#define INV_T 10.0f         // 1 / temperature (0.1)
#define BN_EPS  1e-5f
#define COS_EPS 1e-8f

// Scratch (no allocations allowed -> __device__ globals)
__device__ float g_h[TWON * PD];               // projected pre-BN activations
__device__ __nv_bfloat16 g_znb[TWON * PD];     // row-normalized outputs, bf16 RNE
__device__ float g_sum[2 * PD];                // per-view per-col sum
__device__ float g_sumsq[2 * PD];              // per-view per-col sumsq
__device__ float g_rowsum[TWON];               // sum_j S_ij (diag excluded)
__device__ float g_pos[TWON];                  // S_{i, i^NV}

// ---------------------------------------------------------------------------
// K0: zero accumulators
// ---------------------------------------------------------------------------
__global__ void k_zero() {
    int i = blockIdx.x * 256 + threadIdx.x;
    if (i < TWON) g_rowsum[i] = 0.0f;
    if (i < 2 * PD) { g_sum[i] = 0.0f; g_sumsq[i] = 0.0f; }
}

// ---------------------------------------------------------------------------
// K1: h = concat(x, xt) @ W + b    [8192 x 512] @ [512 x 128]  (fp32 FFMA)
// ---------------------------------------------------------------------------
__global__ __launch_bounds__(256) void k_proj(const float* __restrict__ x,
                                              const float* __restrict__ xt,
                                              const float* __restrict__ W,
                                              const float* __restrict__ bias) {
    __shared__ float As[64][64];   // [k][m]
    __shared__ float Bs[64][64];   // [k][n]
    int tid = threadIdx.x;
    int tx = tid & 15, ty = tid >> 4;
    int m0 = blockIdx.y * 64;
    int n0 = blockIdx.x * 64;

    float acc[4][4] = {};

    for (int k0 = 0; k0 < FD; k0 += 64) {
        #pragma unroll
        for (int f = 0; f < 4; f++) {
            int idx = f * 256 + tid;
            int m  = idx >> 4;
            int k4 = idx & 15;
            int row = m0 + m;
            const float* src = (row < NV) ? (x + (size_t)row * FD)
                                          : (xt + (size_t)(row - NV) * FD);
            float4 v = *(const float4*)(src + k0 + k4 * 4);
            As[k4 * 4 + 0][m] = v.x;
            As[k4 * 4 + 1][m] = v.y;
            As[k4 * 4 + 2][m] = v.z;
            As[k4 * 4 + 3][m] = v.w;
        }
        #pragma unroll
        for (int f = 0; f < 4; f++) {
            int idx = f * 256 + tid;
            int k  = idx >> 4;
            int n4 = idx & 15;
            float4 v = *(const float4*)(W + (size_t)(k0 + k) * PD + n0 + n4 * 4);
            *(float4*)&Bs[k][n4 * 4] = v;
        }
        __syncthreads();

        #pragma unroll 8
        for (int k = 0; k < 64; k++) {
            float4 a = *(float4*)&As[k][ty * 4];
            float4 b = *(float4*)&Bs[k][tx * 4];
            float ar[4] = {a.x, a.y, a.z, a.w};
            float br[4] = {b.x, b.y, b.z, b.w};
            #pragma unroll
            for (int r = 0; r < 4; r++)
                #pragma unroll
                for (int c = 0; c < 4; c++)
                    acc[r][c] = fmaf(ar[r], br[c], acc[r][c]);
        }
        __syncthreads();
    }

    #pragma unroll
    for (int r = 0; r < 4; r++) {
        int row = m0 + ty * 4 + r;
        #pragma unroll
        for (int c = 0; c < 4; c++) {
            int col = n0 + tx * 4 + c;
            g_h[(size_t)row * PD + col] = acc[r][c] + bias[col];
        }
    }
}

// ---------------------------------------------------------------------------
// K2a: per-view column sums / sums of squares
// ---------------------------------------------------------------------------
__global__ void k_stats() {
    int c = threadIdx.x;
    int v = blockIdx.x >> 5;
    int chunk = blockIdx.x & 31;
    int r0 = v * NV + chunk * 128;
    float s = 0.0f, sq = 0.0f;
    for (int r = 0; r < 128; r++) {
        float h = g_h[(size_t)(r0 + r) * PD + c];
        s += h;
        sq += h * h;
    }
    atomicAdd(&g_sum[v * PD + c], s);
    atomicAdd(&g_sumsq[v * PD + c], sq);
}

// ---------------------------------------------------------------------------
// K2b: BN-normalize + cosine row-normalize; emit bf16 (RNE) zn
// ---------------------------------------------------------------------------
__global__ void k_norm(const float* __restrict__ gamma,
                       const float* __restrict__ beta) {
    __shared__ float red[4];
    int c = threadIdx.x;
    int row = blockIdx.x;
    int v = row >> 12;

    float mu   = g_sum[v * PD + c]   * (1.0f / NV);
    float var  = g_sumsq[v * PD + c] * (1.0f / NV) - mu * mu;
    float rstd = rsqrtf(var + BN_EPS);
    float z = gamma[c] * (g_h[(size_t)row * PD + c] - mu) * rstd + beta[c];

    float sq = z * z;
    #pragma unroll
    for (int o = 16; o > 0; o >>= 1)
        sq += __shfl_xor_sync(0xffffffffu, sq, o);
    if ((c & 31) == 0) red[c >> 5] = sq;
    __syncthreads();
    float tot = red[0] + red[1] + red[2] + red[3];
    float inv = 1.0f / fmaxf(sqrtf(tot), COS_EPS);
    g_znb[(size_t)row * PD + c] = __float2bfloat16_rn(z * inv);
}

// ---------------------------------------------------------------------------
// K3: fused sim via mma.sync bf16 (m16n8k16). 128x128 tile per 256-thread CTA,
// occupancy 2 (tile loads of one CTA hide under the other's MMA/epilogue).
// SMEM tiles 128 x 136 bf16 (row stride 68 words == 4 mod 32 -> conflict-free
// quad fragment loads). 8 warps in 4x2 grid; warp tile 32x64 = 2x8 mma grid.
// Epilogue fused: exp, diag-zero, positive-pair capture, row-sum atomics.
// ---------------------------------------------------------------------------
#define SPADB 136                         // bf16 elements per smem row
#define SROWW (SPADB / 2)                 // 68 words per row
#define TILE_WORDS (128 * SROWW)          // words per tile
#define SIM_SMEM_BYTES (2 * TILE_WORDS * 4)

__global__ __launch_bounds__(256, 2) void k_sim_mma() {
    extern __shared__ uint32_t smw[];
    uint32_t* Aw = smw;                   // [128][68] words (bf16x2)
    uint32_t* Bw = smw + TILE_WORDS;
    int tid = threadIdx.x;
    int lane = tid & 31, wid = tid >> 5;
    int i0 = blockIdx.y * 128;
    int j0 = blockIdx.x * 128;

    // Load tiles: each row = 256 B = 16 uint4. 2048 uint4 per tile.
    #pragma unroll
    for (int f = 0; f < 8; f++) {
        int idx = f * 256 + tid;          // 0..2047
        int m  = idx >> 4;                // row 0..127
        int c4 = idx & 15;                // uint4 col 0..15
        uint4 va = *(const uint4*)((const char*)g_znb + ((size_t)(i0 + m) * PD) * 2 + c4 * 16);
        *(uint4*)(Aw + m * SROWW + c4 * 4) = va;
        uint4 vb = *(const uint4*)((const char*)g_znb + ((size_t)(j0 + m) * PD) * 2 + c4 * 16);
        *(uint4*)(Bw + m * SROWW + c4 * 4) = vb;
    }
    __syncthreads();

    int g = lane >> 2, tig = lane & 3;
    int rm = (wid & 3) * 32;              // warp row base (i-local)
    int cn = (wid >> 2) * 64;             // warp col base (j-local)

    float acc[2][8][4] = {};
    // base word pointers for this thread's fragment rows
    const uint32_t* Ab = Aw + (rm + g) * SROWW + tig;
    const uint32_t* Bb = Bw + (cn + g) * SROWW + tig;

    #pragma unroll
    for (int ks = 0; ks < 8; ks++) {      // k0 = ks*16, word offset ks*8
        int kw = ks * 8;
        uint32_t a[2][4];
        #pragma unroll
        for (int mt = 0; mt < 2; mt++) {
            const uint32_t* p = Ab + mt * 16 * SROWW + kw;
            a[mt][0] = p[0];              // (g,      k 2tig..+1)
            a[mt][1] = p[8 * SROWW];      // (g+8,    same k)
            a[mt][2] = p[4];              // (g,      k 2tig+8..+9)
            a[mt][3] = p[8 * SROWW + 4];  // (g+8,    k+8)
        }
        #pragma unroll
        for (int nt = 0; nt < 8; nt++) {
            const uint32_t* q = Bb + nt * 8 * SROWW + kw;
            uint32_t b0 = q[0];           // (n g, k 2tig..+1)
            uint32_t b1 = q[4];           // (n g, k 2tig+8..+9)
            #pragma unroll
            for (int mt = 0; mt < 2; mt++) {
                asm volatile(
                    "mma.sync.aligned.m16n8k16.row.col.f32.bf16.bf16.f32 "
                    "{%0,%1,%2,%3}, {%4,%5,%6,%7}, {%8,%9}, {%0,%1,%2,%3};"
                    : "+f"(acc[mt][nt][0]), "+f"(acc[mt][nt][1]),
                      "+f"(acc[mt][nt][2]), "+f"(acc[mt][nt][3])
                    : "r"(a[mt][0]), "r"(a[mt][1]), "r"(a[mt][2]), "r"(a[mt][3]),
                      "r"(b0), "r"(b1));
            }
        }
    }

    // Epilogue: fragment (mt,nt) regs -> rows r0=g / r1=g+8, cols tig*2+{0,1}
    #pragma unroll
    for (int mt = 0; mt < 2; mt++) {
        int r0 = i0 + rm + mt * 16 + g;
        int r1 = r0 + 8;
        int p0 = r0 ^ NV;
        int p1 = r1 ^ NV;
        float s0 = 0.0f, s1 = 0.0f;
        #pragma unroll
        for (int nt = 0; nt < 8; nt++) {
            int jc = j0 + cn + nt * 8 + tig * 2;
            float v0 = (r0 == jc    ) ? 0.0f : __expf(acc[mt][nt][0] * INV_T);
            float v1 = (r0 == jc + 1) ? 0.0f : __expf(acc[mt][nt][1] * INV_T);
            float v2 = (r1 == jc    ) ? 0.0f : __expf(acc[mt][nt][2] * INV_T);
            float v3 = (r1 == jc + 1) ? 0.0f : __expf(acc[mt][nt][3] * INV_T);
            if (jc     == p0) g_pos[r0] = v0;
            if (jc + 1 == p0) g_pos[r0] = v1;
            if (jc     == p1) g_pos[r1] = v2;
            if (jc + 1 == p1) g_pos[r1] = v3;
            s0 += v0 + v1;
            s1 += v2 + v3;
        }
        s0 += __shfl_xor_sync(0xffffffffu, s0, 1);
        s0 += __shfl_xor_sync(0xffffffffu, s0, 2);
        s1 += __shfl_xor_sync(0xffffffffu, s1, 1);
        s1 += __shfl_xor_sync(0xffffffffu, s1, 2);
        if (tig == 0) {
            atomicAdd(&g_rowsum[r0], s0);
            atomicAdd(&g_rowsum[r1], s1);
        }
    }
}

// ---------------------------------------------------------------------------
// K4: V_i = log(rowsum_i) - log(pos_i)
// ---------------------------------------------------------------------------
__global__ void k_final(float* __restrict__ out) {
    int i = blockIdx.x * 256 + threadIdx.x;
    if (i < TWON) out[i] = logf(g_rowsum[i]) - logf(g_pos[i]);
}

// ---------------------------------------------------------------------------
extern "C" void kernel_launch(void* const* d_in, const int* in_sizes, int n_in,
                              void* d_out, int out_size) {
    const float* x     = (const float*)d_in[0];
    const float* xt    = (const float*)d_in[1];
    const float* W     = (const float*)d_in[2];
    const float* bias  = (const float*)d_in[3];
    const float* gamma = (const float*)d_in[4];
    const float* beta  = (const float*)d_in[5];
    float* out = (float*)d_out;

    cudaFuncSetAttribute(k_sim_mma, cudaFuncAttributeMaxDynamicSharedMemorySize,
                         SIM_SMEM_BYTES);

    k_zero <<<32, 256>>>();
    k_proj <<<dim3(PD / 64, TWON / 64), 256>>>(x, xt, W, bias);
    k_stats<<<64, 128>>>();
    k_norm <<<TWON, 128>>>(gamma, beta);
    k_sim_mma<<<dim3(TWON / 128, TWON / 128), 256, SIM_SMEM_BYTES>>>();
    k_final<<<32, 256>>>(out);
}

// round 6
// speedup vs baseline: 6.0704x; 1.6473x over previous
#include <cuda_runtime.h>
#include <cuda_bf16.h>
#include <math.h>
#include <cstdint>

// Problem constants (shapes fixed by setup_inputs)
#define NV    4096          // batch per view
#define TWON  8192          // 2N rows total
#define FD    512           // feature dim
#define PD    128           // projection dim
#define NB    (TWON / 128)  // 64 tile-blocks per dimension
#define INV_T 10.0f         // 1 / temperature (0.1)
#define BN_EPS  1e-5f
#define COS_EPS 1e-8f

// Scratch (no allocations allowed -> __device__ globals)
__device__ float g_h[TWON * PD];               // projected pre-BN activations
__device__ __nv_bfloat16 g_znb[TWON * PD];     // row-normalized outputs, bf16 RNE
__device__ float g_sum[2 * PD];                // per-view per-col sum
__device__ float g_sumsq[2 * PD];              // per-view per-col sumsq
__device__ float g_rowsum[TWON];               // sum_j S_ij (diag excluded)
__device__ float g_pos[TWON];                  // S_{i, i^NV}

// RNA-rounded tf32 (unbiased)
__device__ __forceinline__ float to_tf32(float x) {
    uint32_t u;
    asm("cvt.rna.tf32.f32 %0, %1;" : "=r"(u) : "f"(x));
    return __uint_as_float(u);
}

// ---------------------------------------------------------------------------
// K0: zero accumulators
// ---------------------------------------------------------------------------
__global__ void k_zero() {
    int i = blockIdx.x * 256 + threadIdx.x;
    if (i < TWON) g_rowsum[i] = 0.0f;
    if (i < 2 * PD) { g_sum[i] = 0.0f; g_sumsq[i] = 0.0f; }
}

// ---------------------------------------------------------------------------
// K1: h = concat(x, xt) @ W + b via tf32 mma.sync, fused BN column stats.
// CTA tile 64x128, BK=64, 256 threads; 8 warps = 2(m) x 4(n), warp 32x32.
// A smem [64][68] f32; W chunk smem [64][136] f32 ([k][n], pad 8 -> LDS
// fragment reads tig*8+g cover all 32 banks).
// ---------------------------------------------------------------------------
#define PAROW 68
#define PBROW 136
#define PROJ_SMEM ((64 * PAROW + 64 * PBROW) * 4)

__global__ __launch_bounds__(256) void k_proj_mma(const float* __restrict__ x,
                                                  const float* __restrict__ xt,
                                                  const float* __restrict__ W,
                                                  const float* __restrict__ bias) {
    extern __shared__ float ps[];
    float* As = ps;                       // [64][PAROW]
    float* Bs = ps + 64 * PAROW;          // [64][PBROW]  ([k][n])
    int tid = threadIdx.x;
    int lane = tid & 31, wid = tid >> 5;
    int g = lane >> 2, tig = lane & 3;
    int m0 = blockIdx.x * 64;
    const float* src = (m0 < NV) ? (x + (size_t)m0 * FD)
                                 : (xt + (size_t)(m0 - NV) * FD);
    int rm = (wid & 1) * 32;              // warp row base (m-local)
    int cn = (wid >> 1) * 32;             // warp col base (n-local)

    float acc[2][4][4] = {};

    for (int k0 = 0; k0 < FD; k0 += 64) {
        // A chunk: 64 rows x 64 k (1024 float4)
        #pragma unroll
        for (int f = 0; f < 4; f++) {
            int idx = f * 256 + tid;
            int m  = idx >> 4;
            int k4 = idx & 15;
            float4 v = *(const float4*)(src + (size_t)m * FD + k0 + k4 * 4);
            v.x = to_tf32(v.x); v.y = to_tf32(v.y);
            v.z = to_tf32(v.z); v.w = to_tf32(v.w);
            *(float4*)(As + m * PAROW + k4 * 4) = v;
        }
        // W chunk: 64 k-rows x 128 n (2048 float4), natural [k][n]
        #pragma unroll
        for (int f = 0; f < 8; f++) {
            int idx = f * 256 + tid;
            int k  = idx >> 5;
            int n4 = idx & 31;
            float4 v = *(const float4*)(W + (size_t)(k0 + k) * PD + n4 * 4);
            v.x = to_tf32(v.x); v.y = to_tf32(v.y);
            v.z = to_tf32(v.z); v.w = to_tf32(v.w);
            *(float4*)(Bs + k * PBROW + n4 * 4) = v;
        }
        __syncthreads();

        #pragma unroll
        for (int ks = 0; ks < 8; ks++) {
            int kb = ks * 8;
            uint32_t a[2][4];
            #pragma unroll
            for (int mt = 0; mt < 2; mt++) {
                const float* p = As + (rm + mt * 16 + g) * PAROW + kb + tig;
                a[mt][0] = __float_as_uint(p[0]);
                a[mt][1] = __float_as_uint(p[8 * PAROW]);
                a[mt][2] = __float_as_uint(p[4]);
                a[mt][3] = __float_as_uint(p[8 * PAROW + 4]);
            }
            #pragma unroll
            for (int nt = 0; nt < 4; nt++) {
                int nn = cn + nt * 8 + g;
                uint32_t b0 = __float_as_uint(Bs[(kb + tig) * PBROW + nn]);
                uint32_t b1 = __float_as_uint(Bs[(kb + tig + 4) * PBROW + nn]);
                #pragma unroll
                for (int mt = 0; mt < 2; mt++) {
                    asm volatile(
                        "mma.sync.aligned.m16n8k8.row.col.f32.tf32.tf32.f32 "
                        "{%0,%1,%2,%3}, {%4,%5,%6,%7}, {%8,%9}, {%0,%1,%2,%3};"
                        : "+f"(acc[mt][nt][0]), "+f"(acc[mt][nt][1]),
                          "+f"(acc[mt][nt][2]), "+f"(acc[mt][nt][3])
                        : "r"(a[mt][0]), "r"(a[mt][1]), "r"(a[mt][2]), "r"(a[mt][3]),
                          "r"(b0), "r"(b1));
                }
            }
        }
        __syncthreads();
    }

    // Epilogue: +bias, store h, fused per-column sum/sumsq (per-view)
    float cs0[4] = {}, cs1[4] = {}, cq0[4] = {}, cq1[4] = {};
    #pragma unroll
    for (int nt = 0; nt < 4; nt++) {
        int jc = cn + nt * 8 + tig * 2;
        float bb0 = bias[jc], bb1 = bias[jc + 1];
        #pragma unroll
        for (int mt = 0; mt < 2; mt++) {
            int r0 = m0 + rm + mt * 16 + g;
            int r1 = r0 + 8;
            float h0 = acc[mt][nt][0] + bb0;
            float h1 = acc[mt][nt][1] + bb1;
            float h2 = acc[mt][nt][2] + bb0;
            float h3 = acc[mt][nt][3] + bb1;
            g_h[(size_t)r0 * PD + jc]     = h0;
            g_h[(size_t)r0 * PD + jc + 1] = h1;
            g_h[(size_t)r1 * PD + jc]     = h2;
            g_h[(size_t)r1 * PD + jc + 1] = h3;
            cs0[nt] += h0 + h2;  cs1[nt] += h1 + h3;
            cq0[nt] += h0 * h0 + h2 * h2;
            cq1[nt] += h1 * h1 + h3 * h3;
        }
    }
    int v = m0 >> 12;
    #pragma unroll
    for (int nt = 0; nt < 4; nt++) {
        float a0 = cs0[nt], a1 = cs1[nt], q0 = cq0[nt], q1 = cq1[nt];
        #pragma unroll
        for (int o = 4; o < 32; o <<= 1) {
            a0 += __shfl_xor_sync(0xffffffffu, a0, o);
            a1 += __shfl_xor_sync(0xffffffffu, a1, o);
            q0 += __shfl_xor_sync(0xffffffffu, q0, o);
            q1 += __shfl_xor_sync(0xffffffffu, q1, o);
        }
        if (g == 0) {
            int jc = cn + nt * 8 + tig * 2;
            atomicAdd(&g_sum[v * PD + jc],       a0);
            atomicAdd(&g_sum[v * PD + jc + 1],   a1);
            atomicAdd(&g_sumsq[v * PD + jc],     q0);
            atomicAdd(&g_sumsq[v * PD + jc + 1], q1);
        }
    }
}

// ---------------------------------------------------------------------------
// K2: BN-normalize + cosine row-normalize; emit bf16 (RNE) zn
// ---------------------------------------------------------------------------
__global__ void k_norm(const float* __restrict__ gamma,
                       const float* __restrict__ beta) {
    __shared__ float red[4];
    int c = threadIdx.x;
    int row = blockIdx.x;
    int v = row >> 12;

    float mu   = g_sum[v * PD + c]   * (1.0f / NV);
    float var  = g_sumsq[v * PD + c] * (1.0f / NV) - mu * mu;
    float rstd = rsqrtf(var + BN_EPS);
    float z = gamma[c] * (g_h[(size_t)row * PD + c] - mu) * rstd + beta[c];

    float sq = z * z;
    #pragma unroll
    for (int o = 16; o > 0; o >>= 1)
        sq += __shfl_xor_sync(0xffffffffu, sq, o);
    if ((c & 31) == 0) red[c >> 5] = sq;
    __syncthreads();
    float tot = red[0] + red[1] + red[2] + red[3];
    float inv = 1.0f / fmaxf(sqrtf(tot), COS_EPS);
    g_znb[(size_t)row * PD + c] = __float2bfloat16_rn(z * inv);
}

// ---------------------------------------------------------------------------
// K3: SYMMETRIC fused sim via bf16 mma (m16n8k16). Only tiles bi <= bj
// (2080 CTAs). Off-diagonal tiles emit row sums (rows of bi) AND column
// sums (rows of bj); diagonal tiles row sums only. One tile covers both
// g_pos[i] and g_pos[j] of a positive pair (equal by symmetry).
// ---------------------------------------------------------------------------
#define SPADB 136                         // bf16 elements per smem row
#define SROWW (SPADB / 2)                 // 68 words per row
#define TILE_WORDS (128 * SROWW)
#define SIM_SMEM_BYTES (2 * TILE_WORDS * 4)

__global__ __launch_bounds__(256, 2) void k_sim_mma() {
    extern __shared__ uint32_t smw[];
    uint32_t* Aw = smw;                   // [128][68] words (bf16x2)
    uint32_t* Bw = smw + TILE_WORDS;
    int tid = threadIdx.x;
    int lane = tid & 31, wid = tid >> 5;

    // decode linear tile id -> (bi, bj), bi <= bj
    int rem = blockIdx.x, bi = 0;
    while (rem >= NB - bi) { rem -= NB - bi; bi++; }
    int bj = bi + rem;
    int i0 = bi * 128;
    int j0 = bj * 128;
    bool offdiag = (bi != bj);

    // Load tiles: each row = 256 B = 16 uint4. 2048 uint4 per tile.
    #pragma unroll
    for (int f = 0; f < 8; f++) {
        int idx = f * 256 + tid;
        int m  = idx >> 4;
        int c4 = idx & 15;
        uint4 va = *(const uint4*)((const char*)g_znb + ((size_t)(i0 + m) * PD) * 2 + c4 * 16);
        *(uint4*)(Aw + m * SROWW + c4 * 4) = va;
        uint4 vb = *(const uint4*)((const char*)g_znb + ((size_t)(j0 + m) * PD) * 2 + c4 * 16);
        *(uint4*)(Bw + m * SROWW + c4 * 4) = vb;
    }
    __syncthreads();

    int g = lane >> 2, tig = lane & 3;
    int rm = (wid & 3) * 32;              // warp row base (i-local)
    int cn = (wid >> 2) * 64;             // warp col base (j-local)

    float acc[2][8][4] = {};
    const uint32_t* Ab = Aw + (rm + g) * SROWW + tig;
    const uint32_t* Bb = Bw + (cn + g) * SROWW + tig;

    #pragma unroll
    for (int ks = 0; ks < 8; ks++) {
        int kw = ks * 8;
        uint32_t a[2][4];
        #pragma unroll
        for (int mt = 0; mt < 2; mt++) {
            const uint32_t* p = Ab + mt * 16 * SROWW + kw;
            a[mt][0] = p[0];
            a[mt][1] = p[8 * SROWW];
            a[mt][2] = p[4];
            a[mt][3] = p[8 * SROWW + 4];
        }
        #pragma unroll
        for (int nt = 0; nt < 8; nt++) {
            const uint32_t* q = Bb + nt * 8 * SROWW + kw;
            uint32_t b0 = q[0];
            uint32_t b1 = q[4];
            #pragma unroll
            for (int mt = 0; mt < 2; mt++) {
                asm volatile(
                    "mma.sync.aligned.m16n8k16.row.col.f32.bf16.bf16.f32 "
                    "{%0,%1,%2,%3}, {%4,%5,%6,%7}, {%8,%9}, {%0,%1,%2,%3};"
                    : "+f"(acc[mt][nt][0]), "+f"(acc[mt][nt][1]),
                      "+f"(acc[mt][nt][2]), "+f"(acc[mt][nt][3])
                    : "r"(a[mt][0]), "r"(a[mt][1]), "r"(a[mt][2]), "r"(a[mt][3]),
                      "r"(b0), "r"(b1));
            }
        }
    }

    // Epilogue. Fragment (mt,nt): rows r0=g / r1=g+8 (+rm,mt16), cols tig*2+{0,1}
    float cp0[8] = {}, cp1[8] = {};       // column partials (for bj rows)
    #pragma unroll
    for (int mt = 0; mt < 2; mt++) {
        int r0 = i0 + rm + mt * 16 + g;
        int r1 = r0 + 8;
        int p0 = r0 ^ NV;
        int p1 = r1 ^ NV;
        float s0 = 0.0f, s1 = 0.0f;
        #pragma unroll
        for (int nt = 0; nt < 8; nt++) {
            int jc = j0 + cn + nt * 8 + tig * 2;
            float v0 = (r0 == jc    ) ? 0.0f : __expf(acc[mt][nt][0] * INV_T);
            float v1 = (r0 == jc + 1) ? 0.0f : __expf(acc[mt][nt][1] * INV_T);
            float v2 = (r1 == jc    ) ? 0.0f : __expf(acc[mt][nt][2] * INV_T);
            float v3 = (r1 == jc + 1) ? 0.0f : __expf(acc[mt][nt][3] * INV_T);
            if (jc     == p0) { g_pos[r0] = v0; g_pos[jc]     = v0; }
            if (jc + 1 == p0) { g_pos[r0] = v1; g_pos[jc + 1] = v1; }
            if (jc     == p1) { g_pos[r1] = v2; g_pos[jc]     = v2; }
            if (jc + 1 == p1) { g_pos[r1] = v3; g_pos[jc + 1] = v3; }
            s0 += v0 + v1;
            s1 += v2 + v3;
            cp0[nt] += v0 + v2;
            cp1[nt] += v1 + v3;
        }
        s0 += __shfl_xor_sync(0xffffffffu, s0, 1);
        s0 += __shfl_xor_sync(0xffffffffu, s0, 2);
        s1 += __shfl_xor_sync(0xffffffffu, s1, 1);
        s1 += __shfl_xor_sync(0xffffffffu, s1, 2);
        if (tig == 0) {
            atomicAdd(&g_rowsum[r0], s0);
            atomicAdd(&g_rowsum[r1], s1);
        }
    }

    if (offdiag) {
        // column sums -> rows of bj tile (S symmetric). Reduce over g (8 rows)
        // then atomics from lanes g==0; the 4 m-warps add independently.
        #pragma unroll
        for (int nt = 0; nt < 8; nt++) {
            float c0 = cp0[nt], c1 = cp1[nt];
            #pragma unroll
            for (int o = 4; o < 32; o <<= 1) {
                c0 += __shfl_xor_sync(0xffffffffu, c0, o);
                c1 += __shfl_xor_sync(0xffffffffu, c1, o);
            }
            if (g == 0) {
                int jc = j0 + cn + nt * 8 + tig * 2;
                atomicAdd(&g_rowsum[jc],     c0);
                atomicAdd(&g_rowsum[jc + 1], c1);
            }
        }
    }
}

// ---------------------------------------------------------------------------
// K4: V_i = log(rowsum_i) - log(pos_i)
// ---------------------------------------------------------------------------
__global__ void k_final(float* __restrict__ out) {
    int i = blockIdx.x * 256 + threadIdx.x;
    if (i < TWON) out[i] = logf(g_rowsum[i]) - logf(g_pos[i]);
}

// ---------------------------------------------------------------------------
extern "C" void kernel_launch(void* const* d_in, const int* in_sizes, int n_in,
                              void* d_out, int out_size) {
    const float* x     = (const float*)d_in[0];
    const float* xt    = (const float*)d_in[1];
    const float* W     = (const float*)d_in[2];
    const float* bias  = (const float*)d_in[3];
    const float* gamma = (const float*)d_in[4];
    const float* beta  = (const float*)d_in[5];
    float* out = (float*)d_out;

    cudaFuncSetAttribute(k_sim_mma, cudaFuncAttributeMaxDynamicSharedMemorySize,
                         SIM_SMEM_BYTES);
    cudaFuncSetAttribute(k_proj_mma, cudaFuncAttributeMaxDynamicSharedMemorySize,
                         PROJ_SMEM);

    const int n_tiles = NB * (NB + 1) / 2;   // 2080

    k_zero <<<32, 256>>>();
    k_proj_mma<<<TWON / 64, 256, PROJ_SMEM>>>(x, xt, W, bias);
    k_norm <<<TWON, 128>>>(gamma, beta);
    k_sim_mma<<<n_tiles, 256, SIM_SMEM_BYTES>>>();
    k_final<<<32, 256>>>(out);
}

// round 7
// speedup vs baseline: 6.4000x; 1.0543x over previous
#include <cuda_runtime.h>
#include <cuda_bf16.h>
#include <math.h>
#include <cstdint>

// Problem constants (shapes fixed by setup_inputs)
#define NV    4096          // batch per view
#define TWON  8192          // 2N rows total
#define FD    512           // feature dim
#define PD    128           // projection dim
#define NB    (TWON / 128)  // 64 tile-blocks per dimension
#define INV_T 10.0f         // 1 / temperature (0.1)
#define BN_EPS  1e-5f
#define COS_EPS 1e-8f

// Scratch (no allocations allowed -> __device__ globals)
__device__ float g_h[TWON * PD];               // projected pre-BN activations
__device__ __nv_bfloat16 g_znb[TWON * PD];     // row-normalized outputs, bf16 RNE
__device__ float g_sum[2 * PD];                // per-view per-col sum
__device__ float g_sumsq[2 * PD];              // per-view per-col sumsq
__device__ float g_rowsum[TWON];               // sum_j S_ij (diag excluded)
__device__ float g_pos[TWON];                  // S_{i, i^NV}

// RNA-rounded tf32 (unbiased)
__device__ __forceinline__ float to_tf32(float x) {
    uint32_t u;
    asm("cvt.rna.tf32.f32 %0, %1;" : "=r"(u) : "f"(x));
    return __uint_as_float(u);
}

__device__ __forceinline__ void ldsm_x4(uint32_t* r, uint32_t addr) {
    asm volatile("ldmatrix.sync.aligned.m8n8.x4.shared.b16 {%0,%1,%2,%3}, [%4];"
                 : "=r"(r[0]), "=r"(r[1]), "=r"(r[2]), "=r"(r[3]) : "r"(addr));
}

// ---------------------------------------------------------------------------
// K0: zero BN stat accumulators (rowsum zeroed in k_norm)
// ---------------------------------------------------------------------------
__global__ void k_zero() {
    int i = blockIdx.x * 256 + threadIdx.x;
    if (i < 2 * PD) { g_sum[i] = 0.0f; g_sumsq[i] = 0.0f; }
}

// ---------------------------------------------------------------------------
// K1: h = concat(x, xt) @ W + b via tf32 mma.sync, fused BN column stats.
// CTA tile 64x128, BK=64, 256 threads; 8 warps = 2(m) x 4(n), warp 32x32.
// ---------------------------------------------------------------------------
#define PAROW 68
#define PBROW 136
#define PROJ_SMEM ((64 * PAROW + 64 * PBROW) * 4)

__global__ __launch_bounds__(256) void k_proj_mma(const float* __restrict__ x,
                                                  const float* __restrict__ xt,
                                                  const float* __restrict__ W,
                                                  const float* __restrict__ bias) {
    extern __shared__ float ps[];
    float* As = ps;                       // [64][PAROW]
    float* Bs = ps + 64 * PAROW;          // [64][PBROW]  ([k][n])
    int tid = threadIdx.x;
    int lane = tid & 31, wid = tid >> 5;
    int g = lane >> 2, tig = lane & 3;
    int m0 = blockIdx.x * 64;
    const float* src = (m0 < NV) ? (x + (size_t)m0 * FD)
                                 : (xt + (size_t)(m0 - NV) * FD);
    int rm = (wid & 1) * 32;              // warp row base (m-local)
    int cn = (wid >> 1) * 32;             // warp col base (n-local)

    float acc[2][4][4] = {};

    for (int k0 = 0; k0 < FD; k0 += 64) {
        #pragma unroll
        for (int f = 0; f < 4; f++) {
            int idx = f * 256 + tid;
            int m  = idx >> 4;
            int k4 = idx & 15;
            float4 v = *(const float4*)(src + (size_t)m * FD + k0 + k4 * 4);
            v.x = to_tf32(v.x); v.y = to_tf32(v.y);
            v.z = to_tf32(v.z); v.w = to_tf32(v.w);
            *(float4*)(As + m * PAROW + k4 * 4) = v;
        }
        #pragma unroll
        for (int f = 0; f < 8; f++) {
            int idx = f * 256 + tid;
            int k  = idx >> 5;
            int n4 = idx & 31;
            float4 v = *(const float4*)(W + (size_t)(k0 + k) * PD + n4 * 4);
            v.x = to_tf32(v.x); v.y = to_tf32(v.y);
            v.z = to_tf32(v.z); v.w = to_tf32(v.w);
            *(float4*)(Bs + k * PBROW + n4 * 4) = v;
        }
        __syncthreads();

        #pragma unroll
        for (int ks = 0; ks < 8; ks++) {
            int kb = ks * 8;
            uint32_t a[2][4];
            #pragma unroll
            for (int mt = 0; mt < 2; mt++) {
                const float* p = As + (rm + mt * 16 + g) * PAROW + kb + tig;
                a[mt][0] = __float_as_uint(p[0]);
                a[mt][1] = __float_as_uint(p[8 * PAROW]);
                a[mt][2] = __float_as_uint(p[4]);
                a[mt][3] = __float_as_uint(p[8 * PAROW + 4]);
            }
            #pragma unroll
            for (int nt = 0; nt < 4; nt++) {
                int nn = cn + nt * 8 + g;
                uint32_t b0 = __float_as_uint(Bs[(kb + tig) * PBROW + nn]);
                uint32_t b1 = __float_as_uint(Bs[(kb + tig + 4) * PBROW + nn]);
                #pragma unroll
                for (int mt = 0; mt < 2; mt++) {
                    asm volatile(
                        "mma.sync.aligned.m16n8k8.row.col.f32.tf32.tf32.f32 "
                        "{%0,%1,%2,%3}, {%4,%5,%6,%7}, {%8,%9}, {%0,%1,%2,%3};"
                        : "+f"(acc[mt][nt][0]), "+f"(acc[mt][nt][1]),
                          "+f"(acc[mt][nt][2]), "+f"(acc[mt][nt][3])
                        : "r"(a[mt][0]), "r"(a[mt][1]), "r"(a[mt][2]), "r"(a[mt][3]),
                          "r"(b0), "r"(b1));
                }
            }
        }
        __syncthreads();
    }

    // Epilogue: +bias, store h, fused per-column sum/sumsq (per-view)
    float cs0[4] = {}, cs1[4] = {}, cq0[4] = {}, cq1[4] = {};
    #pragma unroll
    for (int nt = 0; nt < 4; nt++) {
        int jc = cn + nt * 8 + tig * 2;
        float bb0 = bias[jc], bb1 = bias[jc + 1];
        #pragma unroll
        for (int mt = 0; mt < 2; mt++) {
            int r0 = m0 + rm + mt * 16 + g;
            int r1 = r0 + 8;
            float h0 = acc[mt][nt][0] + bb0;
            float h1 = acc[mt][nt][1] + bb1;
            float h2 = acc[mt][nt][2] + bb0;
            float h3 = acc[mt][nt][3] + bb1;
            g_h[(size_t)r0 * PD + jc]     = h0;
            g_h[(size_t)r0 * PD + jc + 1] = h1;
            g_h[(size_t)r1 * PD + jc]     = h2;
            g_h[(size_t)r1 * PD + jc + 1] = h3;
            cs0[nt] += h0 + h2;  cs1[nt] += h1 + h3;
            cq0[nt] += h0 * h0 + h2 * h2;
            cq1[nt] += h1 * h1 + h3 * h3;
        }
    }
    int v = m0 >> 12;
    #pragma unroll
    for (int nt = 0; nt < 4; nt++) {
        float a0 = cs0[nt], a1 = cs1[nt], q0 = cq0[nt], q1 = cq1[nt];
        #pragma unroll
        for (int o = 4; o < 32; o <<= 1) {
            a0 += __shfl_xor_sync(0xffffffffu, a0, o);
            a1 += __shfl_xor_sync(0xffffffffu, a1, o);
            q0 += __shfl_xor_sync(0xffffffffu, q0, o);
            q1 += __shfl_xor_sync(0xffffffffu, q1, o);
        }
        if (g == 0) {
            int jc = cn + nt * 8 + tig * 2;
            atomicAdd(&g_sum[v * PD + jc],       a0);
            atomicAdd(&g_sum[v * PD + jc + 1],   a1);
            atomicAdd(&g_sumsq[v * PD + jc],     q0);
            atomicAdd(&g_sumsq[v * PD + jc + 1], q1);
        }
    }
}

// ---------------------------------------------------------------------------
// K2: BN-normalize + cosine row-normalize; emit bf16 (RNE) zn.
// 256 threads = 8 rows x 32 lanes; each lane handles 4 cols (float4).
// Also zeroes g_rowsum (must run before k_sim).
// ---------------------------------------------------------------------------
__global__ __launch_bounds__(256) void k_norm(const float* __restrict__ gamma,
                                              const float* __restrict__ beta) {
    int row  = blockIdx.x * 8 + (threadIdx.x >> 5);
    int lane = threadIdx.x & 31;
    int c    = lane * 4;
    int v    = row >> 12;

    float4 h  = *(const float4*)(g_h + (size_t)row * PD + c);
    float4 su = *(const float4*)(g_sum + v * PD + c);
    float4 sq = *(const float4*)(g_sumsq + v * PD + c);
    float4 gm = *(const float4*)(gamma + c);
    float4 bt = *(const float4*)(beta + c);

    float z[4];
    {
        float mu, var;
        mu = su.x * (1.0f / NV); var = sq.x * (1.0f / NV) - mu * mu;
        z[0] = gm.x * (h.x - mu) * rsqrtf(var + BN_EPS) + bt.x;
        mu = su.y * (1.0f / NV); var = sq.y * (1.0f / NV) - mu * mu;
        z[1] = gm.y * (h.y - mu) * rsqrtf(var + BN_EPS) + bt.y;
        mu = su.z * (1.0f / NV); var = sq.z * (1.0f / NV) - mu * mu;
        z[2] = gm.z * (h.z - mu) * rsqrtf(var + BN_EPS) + bt.z;
        mu = su.w * (1.0f / NV); var = sq.w * (1.0f / NV) - mu * mu;
        z[3] = gm.w * (h.w - mu) * rsqrtf(var + BN_EPS) + bt.w;
    }

    float s2 = z[0] * z[0] + z[1] * z[1] + z[2] * z[2] + z[3] * z[3];
    #pragma unroll
    for (int o = 16; o > 0; o >>= 1)
        s2 += __shfl_xor_sync(0xffffffffu, s2, o);
    float inv = 1.0f / fmaxf(sqrtf(s2), COS_EPS);

    __nv_bfloat162 p0 = __floats2bfloat162_rn(z[0] * inv, z[1] * inv);
    __nv_bfloat162 p1 = __floats2bfloat162_rn(z[2] * inv, z[3] * inv);
    uint2 st;
    st.x = *(uint32_t*)&p0;
    st.y = *(uint32_t*)&p1;
    *(uint2*)((char*)g_znb + ((size_t)row * PD + c) * 2) = st;

    if (lane == 0) g_rowsum[row] = 0.0f;
}

// ---------------------------------------------------------------------------
// K3: SYMMETRIC fused sim via bf16 mma (m16n8k16) + ldmatrix fragments.
// Only tiles bi <= bj (2080 CTAs). Off-diagonal tiles emit row sums (bi rows)
// AND column sums (bj rows); diagonal tiles row sums only.
// SMEM row stride 68 words (== 4 mod 32): every 8-lane LDSM phase covers all
// 32 banks; conflict-free.
// ---------------------------------------------------------------------------
#define SPADB 136                         // bf16 elements per smem row
#define SROWW (SPADB / 2)                 // 68 words per row
#define TILE_WORDS (128 * SROWW)
#define SIM_SMEM_BYTES (2 * TILE_WORDS * 4)

__global__ __launch_bounds__(256, 2) void k_sim_mma() {
    extern __shared__ uint32_t smw[];
    uint32_t* Aw = smw;                   // [128][68] words (bf16x2)
    uint32_t* Bw = smw + TILE_WORDS;
    int tid = threadIdx.x;
    int lane = tid & 31, wid = tid >> 5;

    // closed-form decode blockIdx.x -> (bi, bj) with bi <= bj
    // base(bi) = bi*(2*NB+1-bi)/2 ; NB=64 -> bi*(129-bi)/2
    int T = blockIdx.x;
    int bi = (int)((129.0f - sqrtf(16641.0f - 8.0f * (float)T)) * 0.5f);
    while (bi * (129 - bi) / 2 > T) bi--;
    while ((bi + 1) * (128 - bi) / 2 <= T) bi++;
    int bj = bi + (T - bi * (129 - bi) / 2);
    int i0 = bi * 128;
    int j0 = bj * 128;
    bool offdiag = (bi != bj);

    // Load tiles: each row = 256 B = 16 uint4. 2048 uint4 per tile.
    #pragma unroll
    for (int f = 0; f < 8; f++) {
        int idx = f * 256 + tid;
        int m  = idx >> 4;
        int c4 = idx & 15;
        uint4 va = *(const uint4*)((const char*)g_znb + ((size_t)(i0 + m) * PD) * 2 + c4 * 16);
        *(uint4*)(Aw + m * SROWW + c4 * 4) = va;
        uint4 vb = *(const uint4*)((const char*)g_znb + ((size_t)(j0 + m) * PD) * 2 + c4 * 16);
        *(uint4*)(Bw + m * SROWW + c4 * 4) = vb;
    }
    __syncthreads();

    int g = lane >> 2, tig = lane & 3;
    int rm = (wid & 3) * 32;              // warp row base (i-local)
    int cn = (wid >> 2) * 64;             // warp col base (j-local)

    // ldmatrix per-lane addresses: lanes 0-7 -> rows+0..7 @k0, 8-15 -> rows+8
    // @k0, 16-23 -> rows+0..7 @k+8, 24-31 -> rows+8 @k+8.
    uint32_t smem0 = (uint32_t)__cvta_generic_to_shared(smw);
    int frow = ((lane >> 3) & 1) * 8 + (lane & 7);
    int fkw  = ((lane >> 4) & 1) * 4;     // word offset for k+8 group
    uint32_t aAddr = smem0 + (uint32_t)(((rm + frow) * SROWW + fkw) * 4);
    uint32_t bAddr = smem0 + (uint32_t)(TILE_WORDS * 4)
                   + (uint32_t)(((cn + frow) * SROWW + fkw) * 4);
    const uint32_t MT_STRIDE = 16 * SROWW * 4;   // 16 rows

    float acc[2][8][4] = {};

    #pragma unroll
    for (int ks = 0; ks < 8; ks++) {
        uint32_t kb = (uint32_t)(ks * 32);       // 8 words per k-step
        uint32_t a[2][4];
        ldsm_x4(a[0], aAddr + kb);
        ldsm_x4(a[1], aAddr + MT_STRIDE + kb);
        uint32_t b[4][4];
        #pragma unroll
        for (int ntp = 0; ntp < 4; ntp++)
            ldsm_x4(b[ntp], bAddr + ntp * MT_STRIDE + kb);

        #pragma unroll
        for (int ntp = 0; ntp < 4; ntp++) {
            #pragma unroll
            for (int h = 0; h < 2; h++) {        // nt = ntp*2 + h
                uint32_t b0 = b[ntp][h];
                uint32_t b1 = b[ntp][h + 2];
                int nt = ntp * 2 + h;
                #pragma unroll
                for (int mt = 0; mt < 2; mt++) {
                    asm volatile(
                        "mma.sync.aligned.m16n8k16.row.col.f32.bf16.bf16.f32 "
                        "{%0,%1,%2,%3}, {%4,%5,%6,%7}, {%8,%9}, {%0,%1,%2,%3};"
                        : "+f"(acc[mt][nt][0]), "+f"(acc[mt][nt][1]),
                          "+f"(acc[mt][nt][2]), "+f"(acc[mt][nt][3])
                        : "r"(a[mt][0]), "r"(a[mt][1]), "r"(a[mt][2]), "r"(a[mt][3]),
                          "r"(b0), "r"(b1));
                }
            }
        }
    }

    // Epilogue. Fragment (mt,nt): rows r0=g / r1=g+8 (+rm,mt16), cols tig*2+{0,1}
    float cp0[8] = {}, cp1[8] = {};       // column partials (for bj rows)
    #pragma unroll
    for (int mt = 0; mt < 2; mt++) {
        int r0 = i0 + rm + mt * 16 + g;
        int r1 = r0 + 8;
        int p0 = r0 ^ NV;
        int p1 = r1 ^ NV;
        float s0 = 0.0f, s1 = 0.0f;
        #pragma unroll
        for (int nt = 0; nt < 8; nt++) {
            int jc = j0 + cn + nt * 8 + tig * 2;
            float v0 = (r0 == jc    ) ? 0.0f : __expf(acc[mt][nt][0] * INV_T);
            float v1 = (r0 == jc + 1) ? 0.0f : __expf(acc[mt][nt][1] * INV_T);
            float v2 = (r1 == jc    ) ? 0.0f : __expf(acc[mt][nt][2] * INV_T);
            float v3 = (r1 == jc + 1) ? 0.0f : __expf(acc[mt][nt][3] * INV_T);
            if (jc     == p0) { g_pos[r0] = v0; g_pos[jc]     = v0; }
            if (jc + 1 == p0) { g_pos[r0] = v1; g_pos[jc + 1] = v1; }
            if (jc     == p1) { g_pos[r1] = v2; g_pos[jc]     = v2; }
            if (jc + 1 == p1) { g_pos[r1] = v3; g_pos[jc + 1] = v3; }
            s0 += v0 + v1;
            s1 += v2 + v3;
            cp0[nt] += v0 + v2;
            cp1[nt] += v1 + v3;
        }
        s0 += __shfl_xor_sync(0xffffffffu, s0, 1);
        s0 += __shfl_xor_sync(0xffffffffu, s0, 2);
        s1 += __shfl_xor_sync(0xffffffffu, s1, 1);
        s1 += __shfl_xor_sync(0xffffffffu, s1, 2);
        if (tig == 0) {
            atomicAdd(&g_rowsum[r0], s0);
            atomicAdd(&g_rowsum[r1], s1);
        }
    }

    if (offdiag) {
        #pragma unroll
        for (int nt = 0; nt < 8; nt++) {
            float c0 = cp0[nt], c1 = cp1[nt];
            #pragma unroll
            for (int o = 4; o < 32; o <<= 1) {
                c0 += __shfl_xor_sync(0xffffffffu, c0, o);
                c1 += __shfl_xor_sync(0xffffffffu, c1, o);
            }
            if (g == 0) {
                int jc = j0 + cn + nt * 8 + tig * 2;
                atomicAdd(&g_rowsum[jc],     c0);
                atomicAdd(&g_rowsum[jc + 1], c1);
            }
        }
    }
}

// ---------------------------------------------------------------------------
// K4: V_i = log(rowsum_i) - log(pos_i)
// ---------------------------------------------------------------------------
__global__ void k_final(float* __restrict__ out) {
    int i = blockIdx.x * 256 + threadIdx.x;
    if (i < TWON) out[i] = logf(g_rowsum[i]) - logf(g_pos[i]);
}

// ---------------------------------------------------------------------------
extern "C" void kernel_launch(void* const* d_in, const int* in_sizes, int n_in,
                              void* d_out, int out_size) {
    const float* x     = (const float*)d_in[0];
    const float* xt    = (const float*)d_in[1];
    const float* W     = (const float*)d_in[2];
    const float* bias  = (const float*)d_in[3];
    const float* gamma = (const float*)d_in[4];
    const float* beta  = (const float*)d_in[5];
    float* out = (float*)d_out;

    cudaFuncSetAttribute(k_sim_mma, cudaFuncAttributeMaxDynamicSharedMemorySize,
                         SIM_SMEM_BYTES);
    cudaFuncSetAttribute(k_proj_mma, cudaFuncAttributeMaxDynamicSharedMemorySize,
                         PROJ_SMEM);

    const int n_tiles = NB * (NB + 1) / 2;   // 2080

    k_zero <<<1, 256>>>();
    k_proj_mma<<<TWON / 64, 256, PROJ_SMEM>>>(x, xt, W, bias);
    k_norm <<<TWON / 8, 256>>>(gamma, beta);
    k_sim_mma<<<n_tiles, 256, SIM_SMEM_BYTES>>>();
    k_final<<<32, 256>>>(out);
}

// round 9
// speedup vs baseline: 6.9248x; 1.0820x over previous
#include <cuda_runtime.h>
#include <cuda_bf16.h>
#include <math.h>
#include <cstdint>

// Problem constants (shapes fixed by setup_inputs)
#define NV    4096          // batch per view
#define TWON  8192          // 2N rows total
#define FD    512           // feature dim
#define PD    128           // projection dim
#define NB    (TWON / 128)  // 64 tile-blocks per dimension
#define BN_EPS  1e-5f
#define COS_EPS 1e-8f
// exp(sim/T) = 2^(sim * 10 * log2(e))
#define EXP_C 14.426950408889634f

// Scratch (no allocations allowed -> __device__ globals)
__device__ float g_h[TWON * PD];               // projected pre-BN activations
__device__ __nv_bfloat16 g_znb[TWON * PD];     // row-normalized outputs, bf16 RNE
__device__ float g_sum[2 * PD];                // per-view per-col sum
__device__ float g_sumsq[2 * PD];              // per-view per-col sumsq
__device__ float g_rowsum[TWON];               // sum_j S_ij (diag excluded)
__device__ float g_pos[TWON];                  // S_{i, i^NV}

// RNA-rounded tf32 (unbiased)
__device__ __forceinline__ float to_tf32(float x) {
    uint32_t u;
    asm("cvt.rna.tf32.f32 %0, %1;" : "=r"(u) : "f"(x));
    return __uint_as_float(u);
}

__device__ __forceinline__ float ex2(float x) {
    float y;
    asm("ex2.approx.ftz.f32 %0, %1;" : "=f"(y) : "f"(x));
    return y;
}

__device__ __forceinline__ void ldsm_x4(uint32_t* r, uint32_t addr) {
    asm volatile("ldmatrix.sync.aligned.m8n8.x4.shared.b16 {%0,%1,%2,%3}, [%4];"
                 : "=r"(r[0]), "=r"(r[1]), "=r"(r[2]), "=r"(r[3]) : "r"(addr));
}

// ---------------------------------------------------------------------------
// K0: zero BN stat accumulators (rowsum zeroed in k_norm)
// ---------------------------------------------------------------------------
__global__ void k_zero() {
    int i = blockIdx.x * 256 + threadIdx.x;
    if (i < 2 * PD) { g_sum[i] = 0.0f; g_sumsq[i] = 0.0f; }
}

// ---------------------------------------------------------------------------
// K1: h = concat(x, xt) @ W + b via tf32 mma.sync, fused BN column stats.
// CTA tile 64x128, BK=64, 256 threads; 8 warps = 2(m) x 4(n), warp 32x32.
// ---------------------------------------------------------------------------
#define PAROW 68
#define PBROW 136
#define PROJ_SMEM ((64 * PAROW + 64 * PBROW) * 4)

__global__ __launch_bounds__(256) void k_proj_mma(const float* __restrict__ x,
                                                  const float* __restrict__ xt,
                                                  const float* __restrict__ W,
                                                  const float* __restrict__ bias) {
    extern __shared__ float ps[];
    float* As = ps;                       // [64][PAROW]
    float* Bs = ps + 64 * PAROW;          // [64][PBROW]  ([k][n])
    int tid = threadIdx.x;
    int lane = tid & 31, wid = tid >> 5;
    int g = lane >> 2, tig = lane & 3;
    int m0 = blockIdx.x * 64;
    const float* src = (m0 < NV) ? (x + (size_t)m0 * FD)
                                 : (xt + (size_t)(m0 - NV) * FD);
    int rm = (wid & 1) * 32;              // warp row base (m-local)
    int cn = (wid >> 1) * 32;             // warp col base (n-local)

    float acc[2][4][4] = {};

    for (int k0 = 0; k0 < FD; k0 += 64) {
        #pragma unroll
        for (int f = 0; f < 4; f++) {
            int idx = f * 256 + tid;
            int m  = idx >> 4;
            int k4 = idx & 15;
            float4 v = *(const float4*)(src + (size_t)m * FD + k0 + k4 * 4);
            v.x = to_tf32(v.x); v.y = to_tf32(v.y);
            v.z = to_tf32(v.z); v.w = to_tf32(v.w);
            *(float4*)(As + m * PAROW + k4 * 4) = v;
        }
        #pragma unroll
        for (int f = 0; f < 8; f++) {
            int idx = f * 256 + tid;
            int k  = idx >> 5;
            int n4 = idx & 31;
            float4 v = *(const float4*)(W + (size_t)(k0 + k) * PD + n4 * 4);
            v.x = to_tf32(v.x); v.y = to_tf32(v.y);
            v.z = to_tf32(v.z); v.w = to_tf32(v.w);
            *(float4*)(Bs + k * PBROW + n4 * 4) = v;
        }
        __syncthreads();

        #pragma unroll
        for (int ks = 0; ks < 8; ks++) {
            int kb = ks * 8;
            uint32_t a[2][4];
            #pragma unroll
            for (int mt = 0; mt < 2; mt++) {
                const float* p = As + (rm + mt * 16 + g) * PAROW + kb + tig;
                a[mt][0] = __float_as_uint(p[0]);
                a[mt][1] = __float_as_uint(p[8 * PAROW]);
                a[mt][2] = __float_as_uint(p[4]);
                a[mt][3] = __float_as_uint(p[8 * PAROW + 4]);
            }
            #pragma unroll
            for (int nt = 0; nt < 4; nt++) {
                int nn = cn + nt * 8 + g;
                uint32_t b0 = __float_as_uint(Bs[(kb + tig) * PBROW + nn]);
                uint32_t b1 = __float_as_uint(Bs[(kb + tig + 4) * PBROW + nn]);
                #pragma unroll
                for (int mt = 0; mt < 2; mt++) {
                    asm volatile(
                        "mma.sync.aligned.m16n8k8.row.col.f32.tf32.tf32.f32 "
                        "{%0,%1,%2,%3}, {%4,%5,%6,%7}, {%8,%9}, {%0,%1,%2,%3};"
                        : "+f"(acc[mt][nt][0]), "+f"(acc[mt][nt][1]),
                          "+f"(acc[mt][nt][2]), "+f"(acc[mt][nt][3])
                        : "r"(a[mt][0]), "r"(a[mt][1]), "r"(a[mt][2]), "r"(a[mt][3]),
                          "r"(b0), "r"(b1));
                }
            }
        }
        __syncthreads();
    }

    // Epilogue: +bias, store h, fused per-column sum/sumsq (per-view)
    float cs0[4] = {}, cs1[4] = {}, cq0[4] = {}, cq1[4] = {};
    #pragma unroll
    for (int nt = 0; nt < 4; nt++) {
        int jc = cn + nt * 8 + tig * 2;
        float bb0 = bias[jc], bb1 = bias[jc + 1];
        #pragma unroll
        for (int mt = 0; mt < 2; mt++) {
            int r0 = m0 + rm + mt * 16 + g;
            int r1 = r0 + 8;
            float h0 = acc[mt][nt][0] + bb0;
            float h1 = acc[mt][nt][1] + bb1;
            float h2 = acc[mt][nt][2] + bb0;
            float h3 = acc[mt][nt][3] + bb1;
            g_h[(size_t)r0 * PD + jc]     = h0;
            g_h[(size_t)r0 * PD + jc + 1] = h1;
            g_h[(size_t)r1 * PD + jc]     = h2;
            g_h[(size_t)r1 * PD + jc + 1] = h3;
            cs0[nt] += h0 + h2;  cs1[nt] += h1 + h3;
            cq0[nt] += h0 * h0 + h2 * h2;
            cq1[nt] += h1 * h1 + h3 * h3;
        }
    }
    int v = m0 >> 12;
    #pragma unroll
    for (int nt = 0; nt < 4; nt++) {
        float a0 = cs0[nt], a1 = cs1[nt], q0 = cq0[nt], q1 = cq1[nt];
        #pragma unroll
        for (int o = 4; o < 32; o <<= 1) {
            a0 += __shfl_xor_sync(0xffffffffu, a0, o);
            a1 += __shfl_xor_sync(0xffffffffu, a1, o);
            q0 += __shfl_xor_sync(0xffffffffu, q0, o);
            q1 += __shfl_xor_sync(0xffffffffu, q1, o);
        }
        if (g == 0) {
            int jc = cn + nt * 8 + tig * 2;
            atomicAdd(&g_sum[v * PD + jc],       a0);
            atomicAdd(&g_sum[v * PD + jc + 1],   a1);
            atomicAdd(&g_sumsq[v * PD + jc],     q0);
            atomicAdd(&g_sumsq[v * PD + jc + 1], q1);
        }
    }
}

// ---------------------------------------------------------------------------
// K2: BN-normalize + cosine row-normalize; emit bf16 (RNE) zn.
// 256 threads = 8 rows x 32 lanes. Also zeroes g_rowsum.
// ---------------------------------------------------------------------------
__global__ __launch_bounds__(256) void k_norm(const float* __restrict__ gamma,
                                              const float* __restrict__ beta) {
    int row  = blockIdx.x * 8 + (threadIdx.x >> 5);
    int lane = threadIdx.x & 31;
    int c    = lane * 4;
    int v    = row >> 12;

    float4 h  = *(const float4*)(g_h + (size_t)row * PD + c);
    float4 su = *(const float4*)(g_sum + v * PD + c);
    float4 sq = *(const float4*)(g_sumsq + v * PD + c);
    float4 gm = *(const float4*)(gamma + c);
    float4 bt = *(const float4*)(beta + c);

    float z[4];
    {
        float mu, var;
        mu = su.x * (1.0f / NV); var = sq.x * (1.0f / NV) - mu * mu;
        z[0] = gm.x * (h.x - mu) * rsqrtf(var + BN_EPS) + bt.x;
        mu = su.y * (1.0f / NV); var = sq.y * (1.0f / NV) - mu * mu;
        z[1] = gm.y * (h.y - mu) * rsqrtf(var + BN_EPS) + bt.y;
        mu = su.z * (1.0f / NV); var = sq.z * (1.0f / NV) - mu * mu;
        z[2] = gm.z * (h.z - mu) * rsqrtf(var + BN_EPS) + bt.z;
        mu = su.w * (1.0f / NV); var = sq.w * (1.0f / NV) - mu * mu;
        z[3] = gm.w * (h.w - mu) * rsqrtf(var + BN_EPS) + bt.w;
    }

    float s2 = z[0] * z[0] + z[1] * z[1] + z[2] * z[2] + z[3] * z[3];
    #pragma unroll
    for (int o = 16; o > 0; o >>= 1)
        s2 += __shfl_xor_sync(0xffffffffu, s2, o);
    float inv = 1.0f / fmaxf(sqrtf(s2), COS_EPS);

    __nv_bfloat162 p0 = __floats2bfloat162_rn(z[0] * inv, z[1] * inv);
    __nv_bfloat162 p1 = __floats2bfloat162_rn(z[2] * inv, z[3] * inv);
    uint2 st;
    st.x = *(uint32_t*)&p0;
    st.y = *(uint32_t*)&p1;
    *(uint2*)((char*)g_znb + ((size_t)row * PD + c) * 2) = st;

    if (lane == 0) g_rowsum[row] = 0.0f;
}

// ---------------------------------------------------------------------------
// K3: SYMMETRIC fused sim, bf16 mma + ldmatrix, tile-type-specialized epilogue.
// Tile types: DIAG (bi==bj, 64): zero local diag, no column sums.
//             POS  (bj==bi^32, 32): positive pairs on local diag.
//             generic (1984): no compares at all.
// ---------------------------------------------------------------------------
#define SPADB 136
#define SROWW (SPADB / 2)                 // 68 words per row
#define TILE_WORDS (128 * SROWW)
#define SIM_SMEM_BYTES (2 * TILE_WORDS * 4)

template <bool DIAG, bool POS>
__device__ __forceinline__ void sim_epilogue(float acc[2][8][4],
                                             int i0, int j0,
                                             int rm, int cn, int g, int tig) {
    float cp0[8] = {}, cp1[8] = {};
    #pragma unroll
    for (int mt = 0; mt < 2; mt++) {
        int li0 = rm + mt * 16 + g;       // local row
        int li1 = li0 + 8;
        int r0 = i0 + li0, r1 = i0 + li1;
        float s0 = 0.0f, s1 = 0.0f;
        #pragma unroll
        for (int nt = 0; nt < 8; nt++) {
            int lj = cn + nt * 8 + tig * 2;
            float v0 = ex2(acc[mt][nt][0] * EXP_C);
            float v1 = ex2(acc[mt][nt][1] * EXP_C);
            float v2 = ex2(acc[mt][nt][2] * EXP_C);
            float v3 = ex2(acc[mt][nt][3] * EXP_C);
            if (DIAG) {
                if (li0 == lj)     v0 = 0.0f;
                if (li0 == lj + 1) v1 = 0.0f;
                if (li1 == lj)     v2 = 0.0f;
                if (li1 == lj + 1) v3 = 0.0f;
            }
            if (POS) {                    // partner pairs lie on local diagonal
                if (li0 == lj)     { g_pos[r0] = v0; g_pos[j0 + lj]     = v0; }
                if (li0 == lj + 1) { g_pos[r0] = v1; g_pos[j0 + lj + 1] = v1; }
                if (li1 == lj)     { g_pos[r1] = v2; g_pos[j0 + lj]     = v2; }
                if (li1 == lj + 1) { g_pos[r1] = v3; g_pos[j0 + lj + 1] = v3; }
            }
            s0 += v0 + v1;
            s1 += v2 + v3;
            if (!DIAG) { cp0[nt] += v0 + v2; cp1[nt] += v1 + v3; }
        }
        s0 += __shfl_xor_sync(0xffffffffu, s0, 1);
        s0 += __shfl_xor_sync(0xffffffffu, s0, 2);
        s1 += __shfl_xor_sync(0xffffffffu, s1, 1);
        s1 += __shfl_xor_sync(0xffffffffu, s1, 2);
        if (tig == 0) {
            atomicAdd(&g_rowsum[r0], s0);
            atomicAdd(&g_rowsum[r1], s1);
        }
    }
    if (!DIAG) {                          // column sums -> rows of bj (symmetry)
        #pragma unroll
        for (int nt = 0; nt < 8; nt++) {
            float c0 = cp0[nt], c1 = cp1[nt];
            #pragma unroll
            for (int o = 4; o < 32; o <<= 1) {
                c0 += __shfl_xor_sync(0xffffffffu, c0, o);
                c1 += __shfl_xor_sync(0xffffffffu, c1, o);
            }
            if (g == 0) {
                int jc = j0 + cn + nt * 8 + tig * 2;
                atomicAdd(&g_rowsum[jc],     c0);
                atomicAdd(&g_rowsum[jc + 1], c1);
            }
        }
    }
}

__global__ __launch_bounds__(256, 2) void k_sim_mma() {
    extern __shared__ uint32_t smw[];
    uint32_t* Aw = smw;                   // [128][68] words (bf16x2)
    uint32_t* Bw = smw + TILE_WORDS;
    int tid = threadIdx.x;
    int lane = tid & 31, wid = tid >> 5;

    // closed-form decode blockIdx.x -> (bi, bj) with bi <= bj
    int T = blockIdx.x;
    int bi = (int)((129.0f - sqrtf(16641.0f - 8.0f * (float)T)) * 0.5f);
    while (bi * (129 - bi) / 2 > T) bi--;
    while ((bi + 1) * (128 - bi) / 2 <= T) bi++;
    int bj = bi + (T - bi * (129 - bi) / 2);
    int i0 = bi * 128;
    int j0 = bj * 128;

    // Load tiles (synchronous; proven path): each row = 256 B = 16 uint4.
    #pragma unroll
    for (int f = 0; f < 8; f++) {
        int idx = f * 256 + tid;
        int m  = idx >> 4;
        int c4 = idx & 15;
        uint4 va = *(const uint4*)((const char*)g_znb + ((size_t)(i0 + m) * PD) * 2 + c4 * 16);
        *(uint4*)(Aw + m * SROWW + c4 * 4) = va;
        uint4 vb = *(const uint4*)((const char*)g_znb + ((size_t)(j0 + m) * PD) * 2 + c4 * 16);
        *(uint4*)(Bw + m * SROWW + c4 * 4) = vb;
    }
    __syncthreads();

    int g = lane >> 2, tig = lane & 3;
    int rm = (wid & 3) * 32;              // warp row base (i-local)
    int cn = (wid >> 2) * 64;             // warp col base (j-local)

    uint32_t smem0 = (uint32_t)__cvta_generic_to_shared(smw);
    int frow = ((lane >> 3) & 1) * 8 + (lane & 7);
    int fkw  = ((lane >> 4) & 1) * 4;
    uint32_t aAddr = smem0 + (uint32_t)(((rm + frow) * SROWW + fkw) * 4);
    uint32_t bAddr = smem0 + (uint32_t)(TILE_WORDS * 4)
                   + (uint32_t)(((cn + frow) * SROWW + fkw) * 4);
    const uint32_t MT_STRIDE = 16 * SROWW * 4;

    float acc[2][8][4] = {};

    #pragma unroll
    for (int ks = 0; ks < 8; ks++) {
        uint32_t kb = (uint32_t)(ks * 32);
        uint32_t a[2][4];
        ldsm_x4(a[0], aAddr + kb);
        ldsm_x4(a[1], aAddr + MT_STRIDE + kb);
        uint32_t b[4][4];
        #pragma unroll
        for (int ntp = 0; ntp < 4; ntp++)
            ldsm_x4(b[ntp], bAddr + ntp * MT_STRIDE + kb);

        #pragma unroll
        for (int ntp = 0; ntp < 4; ntp++) {
            #pragma unroll
            for (int h = 0; h < 2; h++) {
                uint32_t b0 = b[ntp][h];
                uint32_t b1 = b[ntp][h + 2];
                int nt = ntp * 2 + h;
                #pragma unroll
                for (int mt = 0; mt < 2; mt++) {
                    asm volatile(
                        "mma.sync.aligned.m16n8k16.row.col.f32.bf16.bf16.f32 "
                        "{%0,%1,%2,%3}, {%4,%5,%6,%7}, {%8,%9}, {%0,%1,%2,%3};"
                        : "+f"(acc[mt][nt][0]), "+f"(acc[mt][nt][1]),
                          "+f"(acc[mt][nt][2]), "+f"(acc[mt][nt][3])
                        : "r"(a[mt][0]), "r"(a[mt][1]), "r"(a[mt][2]), "r"(a[mt][3]),
                          "r"(b0), "r"(b1));
                }
            }
        }
    }

    if (bi == bj)
        sim_epilogue<true, false>(acc, i0, j0, rm, cn, g, tig);
    else if (bj == (bi ^ 32))             // NV / 128 = 32
        sim_epilogue<false, true>(acc, i0, j0, rm, cn, g, tig);
    else
        sim_epilogue<false, false>(acc, i0, j0, rm, cn, g, tig);
}

// ---------------------------------------------------------------------------
// K4: V_i = log(rowsum_i) - log(pos_i)
// ---------------------------------------------------------------------------
__global__ void k_final(float* __restrict__ out) {
    int i = blockIdx.x * 256 + threadIdx.x;
    if (i < TWON) out[i] = logf(g_rowsum[i]) - logf(g_pos[i]);
}

// ---------------------------------------------------------------------------
extern "C" void kernel_launch(void* const* d_in, const int* in_sizes, int n_in,
                              void* d_out, int out_size) {
    const float* x     = (const float*)d_in[0];
    const float* xt    = (const float*)d_in[1];
    const float* W     = (const float*)d_in[2];
    const float* bias  = (const float*)d_in[3];
    const float* gamma = (const float*)d_in[4];
    const float* beta  = (const float*)d_in[5];
    float* out = (float*)d_out;

    cudaFuncSetAttribute(k_sim_mma, cudaFuncAttributeMaxDynamicSharedMemorySize,
                         SIM_SMEM_BYTES);
    cudaFuncSetAttribute(k_proj_mma, cudaFuncAttributeMaxDynamicSharedMemorySize,
                         PROJ_SMEM);

    const int n_tiles = NB * (NB + 1) / 2;   // 2080

    k_zero <<<1, 256>>>();
    k_proj_mma<<<TWON / 64, 256, PROJ_SMEM>>>(x, xt, W, bias);
    k_norm <<<TWON / 8, 256>>>(gamma, beta);
    k_sim_mma<<<n_tiles, 256, SIM_SMEM_BYTES>>>();
    k_final<<<32, 256>>>(out);
}

// round 11
// speedup vs baseline: 7.3012x; 1.0544x over previous
#include <cuda_runtime.h>
#include <cuda_bf16.h>
#include <math.h>
#include <cstdint>

// Problem constants (shapes fixed by setup_inputs)
#define NV    4096          // batch per view
#define TWON  8192          // 2N rows total
#define FD    512           // feature dim
#define PD    128           // projection dim
#define NB    (TWON / 128)  // 64 tile-blocks per dimension
#define BN_EPS  1e-5f
#define COS_EPS 1e-8f
// exp(sim/T) = 2^(sim * 10 * log2(e))
#define EXP_C 14.426950408889634f

// Scratch (no allocations allowed -> __device__ globals)
__device__ float g_h[TWON * PD];               // projected pre-BN activations
__device__ __nv_bfloat16 g_znb[TWON * PD];     // row-normalized outputs, bf16 RNE
__device__ float g_sum[2 * PD];                // per-view per-col sum (zeroed by k_final)
__device__ float g_sumsq[2 * PD];              // per-view per-col sumsq (zeroed by k_final)
__device__ float g_rowsum[TWON];               // sum_j S_ij (diag excluded)
__device__ float g_pos[TWON];                  // S_{i, i^NV}

// RNA-rounded tf32 (unbiased)
__device__ __forceinline__ float to_tf32(float x) {
    uint32_t u;
    asm("cvt.rna.tf32.f32 %0, %1;" : "=r"(u) : "f"(x));
    return __uint_as_float(u);
}

__device__ __forceinline__ float ex2(float x) {
    float y;
    asm("ex2.approx.ftz.f32 %0, %1;" : "=f"(y) : "f"(x));
    return y;
}

__device__ __forceinline__ void ldsm_x4(uint32_t* r, uint32_t addr) {
    asm volatile("ldmatrix.sync.aligned.m8n8.x4.shared.b16 {%0,%1,%2,%3}, [%4];"
                 : "=r"(r[0]), "=r"(r[1]), "=r"(r[2]), "=r"(r[3]) : "r"(addr));
}

// ---------------------------------------------------------------------------
// K1: h = concat(x, xt) @ W + b via tf32 mma.sync, fused BN column stats.
// CTA tile 64x128, BK=64, 256 threads; 8 warps = 2(m) x 4(n), warp 32x32.
// ---------------------------------------------------------------------------
#define PAROW 68
#define PBROW 136
#define PROJ_SMEM ((64 * PAROW + 64 * PBROW) * 4)

__global__ __launch_bounds__(256) void k_proj_mma(const float* __restrict__ x,
                                                  const float* __restrict__ xt,
                                                  const float* __restrict__ W,
                                                  const float* __restrict__ bias) {
    extern __shared__ float ps[];
    float* As = ps;                       // [64][PAROW]
    float* Bs = ps + 64 * PAROW;          // [64][PBROW]  ([k][n])
    int tid = threadIdx.x;
    int lane = tid & 31, wid = tid >> 5;
    int g = lane >> 2, tig = lane & 3;
    int m0 = blockIdx.x * 64;
    const float* src = (m0 < NV) ? (x + (size_t)m0 * FD)
                                 : (xt + (size_t)(m0 - NV) * FD);
    int rm = (wid & 1) * 32;              // warp row base (m-local)
    int cn = (wid >> 1) * 32;             // warp col base (n-local)

    float acc[2][4][4] = {};

    for (int k0 = 0; k0 < FD; k0 += 64) {
        #pragma unroll
        for (int f = 0; f < 4; f++) {
            int idx = f * 256 + tid;
            int m  = idx >> 4;
            int k4 = idx & 15;
            float4 v = *(const float4*)(src + (size_t)m * FD + k0 + k4 * 4);
            v.x = to_tf32(v.x); v.y = to_tf32(v.y);
            v.z = to_tf32(v.z); v.w = to_tf32(v.w);
            *(float4*)(As + m * PAROW + k4 * 4) = v;
        }
        #pragma unroll
        for (int f = 0; f < 8; f++) {
            int idx = f * 256 + tid;
            int k  = idx >> 5;
            int n4 = idx & 31;
            float4 v = *(const float4*)(W + (size_t)(k0 + k) * PD + n4 * 4);
            v.x = to_tf32(v.x); v.y = to_tf32(v.y);
            v.z = to_tf32(v.z); v.w = to_tf32(v.w);
            *(float4*)(Bs + k * PBROW + n4 * 4) = v;
        }
        __syncthreads();

        #pragma unroll
        for (int ks = 0; ks < 8; ks++) {
            int kb = ks * 8;
            uint32_t a[2][4];
            #pragma unroll
            for (int mt = 0; mt < 2; mt++) {
                const float* p = As + (rm + mt * 16 + g) * PAROW + kb + tig;
                a[mt][0] = __float_as_uint(p[0]);
                a[mt][1] = __float_as_uint(p[8 * PAROW]);
                a[mt][2] = __float_as_uint(p[4]);
                a[mt][3] = __float_as_uint(p[8 * PAROW + 4]);
            }
            #pragma unroll
            for (int nt = 0; nt < 4; nt++) {
                int nn = cn + nt * 8 + g;
                uint32_t b0 = __float_as_uint(Bs[(kb + tig) * PBROW + nn]);
                uint32_t b1 = __float_as_uint(Bs[(kb + tig + 4) * PBROW + nn]);
                #pragma unroll
                for (int mt = 0; mt < 2; mt++) {
                    asm volatile(
                        "mma.sync.aligned.m16n8k8.row.col.f32.tf32.tf32.f32 "
                        "{%0,%1,%2,%3}, {%4,%5,%6,%7}, {%8,%9}, {%0,%1,%2,%3};"
                        : "+f"(acc[mt][nt][0]), "+f"(acc[mt][nt][1]),
                          "+f"(acc[mt][nt][2]), "+f"(acc[mt][nt][3])
                        : "r"(a[mt][0]), "r"(a[mt][1]), "r"(a[mt][2]), "r"(a[mt][3]),
                          "r"(b0), "r"(b1));
                }
            }
        }
        __syncthreads();
    }

    // Epilogue: +bias, store h, fused per-column sum/sumsq (per-view)
    float cs0[4] = {}, cs1[4] = {}, cq0[4] = {}, cq1[4] = {};
    #pragma unroll
    for (int nt = 0; nt < 4; nt++) {
        int jc = cn + nt * 8 + tig * 2;
        float bb0 = bias[jc], bb1 = bias[jc + 1];
        #pragma unroll
        for (int mt = 0; mt < 2; mt++) {
            int r0 = m0 + rm + mt * 16 + g;
            int r1 = r0 + 8;
            float h0 = acc[mt][nt][0] + bb0;
            float h1 = acc[mt][nt][1] + bb1;
            float h2 = acc[mt][nt][2] + bb0;
            float h3 = acc[mt][nt][3] + bb1;
            g_h[(size_t)r0 * PD + jc]     = h0;
            g_h[(size_t)r0 * PD + jc + 1] = h1;
            g_h[(size_t)r1 * PD + jc]     = h2;
            g_h[(size_t)r1 * PD + jc + 1] = h3;
            cs0[nt] += h0 + h2;  cs1[nt] += h1 + h3;
            cq0[nt] += h0 * h0 + h2 * h2;
            cq1[nt] += h1 * h1 + h3 * h3;
        }
    }
    int v = m0 >> 12;
    #pragma unroll
    for (int nt = 0; nt < 4; nt++) {
        float a0 = cs0[nt], a1 = cs1[nt], q0 = cq0[nt], q1 = cq1[nt];
        #pragma unroll
        for (int o = 4; o < 32; o <<= 1) {
            a0 += __shfl_xor_sync(0xffffffffu, a0, o);
            a1 += __shfl_xor_sync(0xffffffffu, a1, o);
            q0 += __shfl_xor_sync(0xffffffffu, q0, o);
            q1 += __shfl_xor_sync(0xffffffffu, q1, o);
        }
        if (g == 0) {
            int jc = cn + nt * 8 + tig * 2;
            atomicAdd(&g_sum[v * PD + jc],       a0);
            atomicAdd(&g_sum[v * PD + jc + 1],   a1);
            atomicAdd(&g_sumsq[v * PD + jc],     q0);
            atomicAdd(&g_sumsq[v * PD + jc + 1], q1);
        }
    }
}

// ---------------------------------------------------------------------------
// K2: BN-normalize + cosine row-normalize; emit bf16 (RNE) zn.
// 256 threads = 8 rows x 32 lanes. Also zeroes g_rowsum.
// ---------------------------------------------------------------------------
__global__ __launch_bounds__(256) void k_norm(const float* __restrict__ gamma,
                                              const float* __restrict__ beta) {
    int row  = blockIdx.x * 8 + (threadIdx.x >> 5);
    int lane = threadIdx.x & 31;
    int c    = lane * 4;
    int v    = row >> 12;

    float4 h  = *(const float4*)(g_h + (size_t)row * PD + c);
    float4 su = *(const float4*)(g_sum + v * PD + c);
    float4 sq = *(const float4*)(g_sumsq + v * PD + c);
    float4 gm = *(const float4*)(gamma + c);
    float4 bt = *(const float4*)(beta + c);

    float z[4];
    {
        float mu, var;
        mu = su.x * (1.0f / NV); var = sq.x * (1.0f / NV) - mu * mu;
        z[0] = gm.x * (h.x - mu) * rsqrtf(var + BN_EPS) + bt.x;
        mu = su.y * (1.0f / NV); var = sq.y * (1.0f / NV) - mu * mu;
        z[1] = gm.y * (h.y - mu) * rsqrtf(var + BN_EPS) + bt.y;
        mu = su.z * (1.0f / NV); var = sq.z * (1.0f / NV) - mu * mu;
        z[2] = gm.z * (h.z - mu) * rsqrtf(var + BN_EPS) + bt.z;
        mu = su.w * (1.0f / NV); var = sq.w * (1.0f / NV) - mu * mu;
        z[3] = gm.w * (h.w - mu) * rsqrtf(var + BN_EPS) + bt.w;
    }

    float s2 = z[0] * z[0] + z[1] * z[1] + z[2] * z[2] + z[3] * z[3];
    #pragma unroll
    for (int o = 16; o > 0; o >>= 1)
        s2 += __shfl_xor_sync(0xffffffffu, s2, o);
    float inv = 1.0f / fmaxf(sqrtf(s2), COS_EPS);

    __nv_bfloat162 p0 = __floats2bfloat162_rn(z[0] * inv, z[1] * inv);
    __nv_bfloat162 p1 = __floats2bfloat162_rn(z[2] * inv, z[3] * inv);
    uint2 st;
    st.x = *(uint32_t*)&p0;
    st.y = *(uint32_t*)&p1;
    *(uint2*)((char*)g_znb + ((size_t)row * PD + c) * 2) = st;

    if (lane == 0) g_rowsum[row] = 0.0f;
}

// ---------------------------------------------------------------------------
// K3: SYMMETRIC fused sim, bf16 mma + ldmatrix, PAIRED j-tiles per CTA.
// CTA handles (bi, bj0=bi+2p) and (bi, bj0+1): A tile loaded once, both B
// tiles loaded up-front (one sync for two output tiles). Tile1 is provably
// generic (DIAG only at p=0 tile0; POS offset 32 is even -> tile0 only).
// Row-sum reduction deferred across both tiles -> one atomic set per CTA.
// ---------------------------------------------------------------------------
#define SPADB 136
#define SROWW (SPADB / 2)                 // 68 words per row
#define TILE_WORDS (128 * SROWW)
#define SIM_SMEM_BYTES (3 * TILE_WORDS * 4)

__device__ __forceinline__ void sim_mainloop(float acc[2][8][4],
                                             uint32_t aAddr, uint32_t bAddr) {
    const uint32_t MT_STRIDE = 16 * SROWW * 4;
    #pragma unroll
    for (int mt = 0; mt < 2; mt++)
        #pragma unroll
        for (int nt = 0; nt < 8; nt++)
            #pragma unroll
            for (int c = 0; c < 4; c++)
                acc[mt][nt][c] = 0.0f;

    #pragma unroll
    for (int ks = 0; ks < 8; ks++) {
        uint32_t kb = (uint32_t)(ks * 32);
        uint32_t a[2][4];
        ldsm_x4(a[0], aAddr + kb);
        ldsm_x4(a[1], aAddr + MT_STRIDE + kb);
        uint32_t b[4][4];
        #pragma unroll
        for (int ntp = 0; ntp < 4; ntp++)
            ldsm_x4(b[ntp], bAddr + ntp * MT_STRIDE + kb);

        #pragma unroll
        for (int ntp = 0; ntp < 4; ntp++) {
            #pragma unroll
            for (int h = 0; h < 2; h++) {
                uint32_t b0 = b[ntp][h];
                uint32_t b1 = b[ntp][h + 2];
                int nt = ntp * 2 + h;
                #pragma unroll
                for (int mt = 0; mt < 2; mt++) {
                    asm volatile(
                        "mma.sync.aligned.m16n8k16.row.col.f32.bf16.bf16.f32 "
                        "{%0,%1,%2,%3}, {%4,%5,%6,%7}, {%8,%9}, {%0,%1,%2,%3};"
                        : "+f"(acc[mt][nt][0]), "+f"(acc[mt][nt][1]),
                          "+f"(acc[mt][nt][2]), "+f"(acc[mt][nt][3])
                        : "r"(a[mt][0]), "r"(a[mt][1]), "r"(a[mt][2]), "r"(a[mt][3]),
                          "r"(b0), "r"(b1));
                }
            }
        }
    }
}

// Per-tile epilogue: exp + (diag/pos handling) + column atomics; row partial
// sums accumulate into rs[mt][half] for a single deferred row-atomic pass.
template <bool DIAG, bool POS>
__device__ __forceinline__ void sim_tile_epi(float acc[2][8][4],
                                             int i0, int j0,
                                             int rm, int cn, int g, int tig,
                                             float rs[2][2]) {
    float cp0[8] = {}, cp1[8] = {};
    #pragma unroll
    for (int mt = 0; mt < 2; mt++) {
        int li0 = rm + mt * 16 + g;       // local row
        int li1 = li0 + 8;
        int r0 = i0 + li0, r1 = i0 + li1;
        float s0 = 0.0f, s1 = 0.0f;
        #pragma unroll
        for (int nt = 0; nt < 8; nt++) {
            int lj = cn + nt * 8 + tig * 2;
            float v0 = ex2(acc[mt][nt][0] * EXP_C);
            float v1 = ex2(acc[mt][nt][1] * EXP_C);
            float v2 = ex2(acc[mt][nt][2] * EXP_C);
            float v3 = ex2(acc[mt][nt][3] * EXP_C);
            if (DIAG) {
                if (li0 == lj)     v0 = 0.0f;
                if (li0 == lj + 1) v1 = 0.0f;
                if (li1 == lj)     v2 = 0.0f;
                if (li1 == lj + 1) v3 = 0.0f;
            }
            if (POS) {                    // partner pairs lie on local diagonal
                if (li0 == lj)     { g_pos[r0] = v0; g_pos[j0 + lj]     = v0; }
                if (li0 == lj + 1) { g_pos[r0] = v1; g_pos[j0 + lj + 1] = v1; }
                if (li1 == lj)     { g_pos[r1] = v2; g_pos[j0 + lj]     = v2; }
                if (li1 == lj + 1) { g_pos[r1] = v3; g_pos[j0 + lj + 1] = v3; }
            }
            s0 += v0 + v1;
            s1 += v2 + v3;
            if (!DIAG) { cp0[nt] += v0 + v2; cp1[nt] += v1 + v3; }
        }
        rs[mt][0] += s0;
        rs[mt][1] += s1;
    }
    if (!DIAG) {                          // column sums -> rows of bj (symmetry)
        #pragma unroll
        for (int nt = 0; nt < 8; nt++) {
            float c0 = cp0[nt], c1 = cp1[nt];
            #pragma unroll
            for (int o = 4; o < 32; o <<= 1) {
                c0 += __shfl_xor_sync(0xffffffffu, c0, o);
                c1 += __shfl_xor_sync(0xffffffffu, c1, o);
            }
            if (g == 0) {
                int jc = j0 + cn + nt * 8 + tig * 2;
                atomicAdd(&g_rowsum[jc],     c0);
                atomicAdd(&g_rowsum[jc + 1], c1);
            }
        }
    }
}

__global__ __launch_bounds__(256, 2) void k_sim_mma() {
    extern __shared__ uint32_t smw[];
    int tid = threadIdx.x;
    int lane = tid & 31, wid = tid >> 5;

    // decode blockIdx.x -> (bi, pair p); row bi has ceil((NB-bi)/2) pairs
    int T = blockIdx.x, bi = 0;
    for (;;) {
        int np = (NB + 1 - bi) >> 1;
        if (T < np) break;
        T -= np; bi++;
    }
    int bj0 = bi + 2 * T;
    int bj1 = bj0 + 1;
    bool has2 = (bj1 < NB);
    int i0  = bi * 128;
    int j00 = bj0 * 128;
    int j01 = bj1 * 128;

    uint32_t smem0 = (uint32_t)__cvta_generic_to_shared(smw);

    // Load A + B0 (+B1): each tile row = 256 B = 16 uint4; 2048 uint4/tile.
    #pragma unroll
    for (int f = 0; f < 8; f++) {
        int idx = f * 256 + tid;
        int m  = idx >> 4;
        int c4 = idx & 15;
        uint32_t soff = (uint32_t)((m * SROWW + c4 * 4) * 4);
        uint4 va = *(const uint4*)((const char*)g_znb + ((size_t)(i0 + m) * PD) * 2 + c4 * 16);
        *(uint4*)((char*)smw + soff) = va;
        uint4 vb = *(const uint4*)((const char*)g_znb + ((size_t)(j00 + m) * PD) * 2 + c4 * 16);
        *(uint4*)((char*)smw + TILE_WORDS * 4 + soff) = vb;
    }
    if (has2) {
        #pragma unroll
        for (int f = 0; f < 8; f++) {
            int idx = f * 256 + tid;
            int m  = idx >> 4;
            int c4 = idx & 15;
            uint32_t soff = (uint32_t)((m * SROWW + c4 * 4) * 4);
            uint4 vc = *(const uint4*)((const char*)g_znb + ((size_t)(j01 + m) * PD) * 2 + c4 * 16);
            *(uint4*)((char*)smw + 2 * TILE_WORDS * 4 + soff) = vc;
        }
    }
    __syncthreads();

    int g = lane >> 2, tig = lane & 3;
    int rm = (wid & 3) * 32;              // warp row base (i-local)
    int cn = (wid >> 2) * 64;             // warp col base (j-local)

    int frow = ((lane >> 3) & 1) * 8 + (lane & 7);
    int fkw  = ((lane >> 4) & 1) * 4;
    uint32_t aAddr  = smem0 + (uint32_t)(((rm + frow) * SROWW + fkw) * 4);
    uint32_t b0Addr = smem0 + (uint32_t)(TILE_WORDS * 4)
                    + (uint32_t)(((cn + frow) * SROWW + fkw) * 4);
    uint32_t b1Addr = b0Addr + (uint32_t)(TILE_WORDS * 4);

    float acc[2][8][4];
    float rs[2][2] = {};                  // deferred row partial sums

    // Tile 0 (may be DIAG at p==0, or POS at bj0-bi==32)
    sim_mainloop(acc, aAddr, b0Addr);
    if (bj0 == bi)
        sim_tile_epi<true, false>(acc, i0, j00, rm, cn, g, tig, rs);
    else if (bj0 == (bi ^ 32))
        sim_tile_epi<false, true>(acc, i0, j00, rm, cn, g, tig, rs);
    else
        sim_tile_epi<false, false>(acc, i0, j00, rm, cn, g, tig, rs);

    // Tile 1 (always generic: bj1-bi odd, != 0 and != 32)
    if (has2) {
        sim_mainloop(acc, aAddr, b1Addr);
        sim_tile_epi<false, false>(acc, i0, j01, rm, cn, g, tig, rs);
    }

    // Deferred row sums (rows of bi tile; combined over both tiles)
    #pragma unroll
    for (int mt = 0; mt < 2; mt++) {
        float s0 = rs[mt][0], s1 = rs[mt][1];
        s0 += __shfl_xor_sync(0xffffffffu, s0, 1);
        s0 += __shfl_xor_sync(0xffffffffu, s0, 2);
        s1 += __shfl_xor_sync(0xffffffffu, s1, 1);
        s1 += __shfl_xor_sync(0xffffffffu, s1, 2);
        if (tig == 0) {
            int r0 = i0 + rm + mt * 16 + g;
            atomicAdd(&g_rowsum[r0], s0);
            atomicAdd(&g_rowsum[r0 + 8], s1);
        }
    }
}

// ---------------------------------------------------------------------------
// K4: V_i = log(rowsum_i) - log(pos_i); also re-zero BN stat accumulators for
// the next invocation (initial zero comes from static init of device globals;
// every call exits with them zeroed -> deterministic under graph replay).
// ---------------------------------------------------------------------------
__global__ void k_final(float* __restrict__ out) {
    int i = blockIdx.x * 256 + threadIdx.x;
    if (i < TWON) out[i] = logf(g_rowsum[i]) - logf(g_pos[i]);
    if (blockIdx.x == 0) {
        g_sum[threadIdx.x]   = 0.0f;      // 256 threads cover 2*PD = 256
        g_sumsq[threadIdx.x] = 0.0f;
    }
}

// ---------------------------------------------------------------------------
extern "C" void kernel_launch(void* const* d_in, const int* in_sizes, int n_in,
                              void* d_out, int out_size) {
    const float* x     = (const float*)d_in[0];
    const float* xt    = (const float*)d_in[1];
    const float* W     = (const float*)d_in[2];
    const float* bias  = (const float*)d_in[3];
    const float* gamma = (const float*)d_in[4];
    const float* beta  = (const float*)d_in[5];
    float* out = (float*)d_out;

    cudaFuncSetAttribute(k_sim_mma, cudaFuncAttributeMaxDynamicSharedMemorySize,
                         SIM_SMEM_BYTES);
    cudaFuncSetAttribute(k_proj_mma, cudaFuncAttributeMaxDynamicSharedMemorySize,
                         PROJ_SMEM);

    // grid = sum over bi of ceil((NB-bi)/2) = 1056
    int n_ctas = 0;
    for (int b = 0; b < NB; b++) n_ctas += (NB + 1 - b) >> 1;

    k_proj_mma<<<TWON / 64, 256, PROJ_SMEM>>>(x, xt, W, bias);
    k_norm <<<TWON / 8, 256>>>(gamma, beta);
    k_sim_mma<<<n_ctas, 256, SIM_SMEM_BYTES>>>();
    k_final<<<32, 256>>>(out);
}

// round 13
// speedup vs baseline: 7.6920x; 1.0535x over previous
#include <cuda_runtime.h>
#include <cuda_bf16.h>
#include <math.h>
#include <cstdint>

// Problem constants (shapes fixed by setup_inputs)
#define NV    4096          // batch per view
#define TWON  8192          // 2N rows total
#define FD    512           // feature dim
#define PD    128           // projection dim
#define NB    (TWON / 128)  // 64 tile-blocks per dimension
#define BN_EPS  1e-5f
#define COS_EPS 1e-8f
// exp(sim/T) = 2^(sim * 10 * log2(e));  zn is pre-scaled by sqrt of this
#define SQRT_EXP_C 3.7982825f          // sqrt(14.426950408889634)
#define LN2F 0.69314718056f

// Scratch (no allocations allowed -> __device__ globals)
__device__ float g_h[TWON * PD];               // projected pre-BN activations
__device__ __nv_bfloat16 g_znb[TWON * PD];     // sqrt(EXP_C)-scaled normalized rows
__device__ float g_sum[2 * PD];                // per-view per-col sum (zeroed by k_final)
__device__ float g_sumsq[2 * PD];              // per-view per-col sumsq (zeroed by k_final)
__device__ float g_rowsum[TWON];               // sum_j S_ij (diag excluded)
__device__ float g_pos[TWON];                  // S_{i, i^NV}

// RNA-rounded tf32 (unbiased)
__device__ __forceinline__ float to_tf32(float x) {
    uint32_t u;
    asm("cvt.rna.tf32.f32 %0, %1;" : "=r"(u) : "f"(x));
    return __uint_as_float(u);
}

__device__ __forceinline__ float ex2(float x) {
    float y;
    asm("ex2.approx.ftz.f32 %0, %1;" : "=f"(y) : "f"(x));
    return y;
}

__device__ __forceinline__ void ldsm_x4(uint32_t* r, uint32_t addr) {
    asm volatile("ldmatrix.sync.aligned.m8n8.x4.shared.b16 {%0,%1,%2,%3}, [%4];"
                 : "=r"(r[0]), "=r"(r[1]), "=r"(r[2]), "=r"(r[3]) : "r"(addr));
}

// ---------------------------------------------------------------------------
// K1: h = concat(x, xt) @ W + b via tf32 mma.sync, fused BN column stats.
// CTA tile 64x128, BK=64, 256 threads; 8 warps = 2(m) x 4(n), warp 32x32.
// ---------------------------------------------------------------------------
#define PAROW 68
#define PBROW 136
#define PROJ_SMEM ((64 * PAROW + 64 * PBROW) * 4)

__global__ __launch_bounds__(256) void k_proj_mma(const float* __restrict__ x,
                                                  const float* __restrict__ xt,
                                                  const float* __restrict__ W,
                                                  const float* __restrict__ bias) {
    extern __shared__ float ps[];
    float* As = ps;                       // [64][PAROW]
    float* Bs = ps + 64 * PAROW;          // [64][PBROW]  ([k][n])
    int tid = threadIdx.x;
    int lane = tid & 31, wid = tid >> 5;
    int g = lane >> 2, tig = lane & 3;
    int m0 = blockIdx.x * 64;
    const float* src = (m0 < NV) ? (x + (size_t)m0 * FD)
                                 : (xt + (size_t)(m0 - NV) * FD);
    int rm = (wid & 1) * 32;              // warp row base (m-local)
    int cn = (wid >> 1) * 32;             // warp col base (n-local)

    float acc[2][4][4] = {};

    for (int k0 = 0; k0 < FD; k0 += 64) {
        #pragma unroll
        for (int f = 0; f < 4; f++) {
            int idx = f * 256 + tid;
            int m  = idx >> 4;
            int k4 = idx & 15;
            float4 v = *(const float4*)(src + (size_t)m * FD + k0 + k4 * 4);
            v.x = to_tf32(v.x); v.y = to_tf32(v.y);
            v.z = to_tf32(v.z); v.w = to_tf32(v.w);
            *(float4*)(As + m * PAROW + k4 * 4) = v;
        }
        #pragma unroll
        for (int f = 0; f < 8; f++) {
            int idx = f * 256 + tid;
            int k  = idx >> 5;
            int n4 = idx & 31;
            float4 v = *(const float4*)(W + (size_t)(k0 + k) * PD + n4 * 4);
            v.x = to_tf32(v.x); v.y = to_tf32(v.y);
            v.z = to_tf32(v.z); v.w = to_tf32(v.w);
            *(float4*)(Bs + k * PBROW + n4 * 4) = v;
        }
        __syncthreads();

        #pragma unroll
        for (int ks = 0; ks < 8; ks++) {
            int kb = ks * 8;
            uint32_t a[2][4];
            #pragma unroll
            for (int mt = 0; mt < 2; mt++) {
                const float* p = As + (rm + mt * 16 + g) * PAROW + kb + tig;
                a[mt][0] = __float_as_uint(p[0]);
                a[mt][1] = __float_as_uint(p[8 * PAROW]);
                a[mt][2] = __float_as_uint(p[4]);
                a[mt][3] = __float_as_uint(p[8 * PAROW + 4]);
            }
            #pragma unroll
            for (int nt = 0; nt < 4; nt++) {
                int nn = cn + nt * 8 + g;
                uint32_t b0 = __float_as_uint(Bs[(kb + tig) * PBROW + nn]);
                uint32_t b1 = __float_as_uint(Bs[(kb + tig + 4) * PBROW + nn]);
                #pragma unroll
                for (int mt = 0; mt < 2; mt++) {
                    asm volatile(
                        "mma.sync.aligned.m16n8k8.row.col.f32.tf32.tf32.f32 "
                        "{%0,%1,%2,%3}, {%4,%5,%6,%7}, {%8,%9}, {%0,%1,%2,%3};"
                        : "+f"(acc[mt][nt][0]), "+f"(acc[mt][nt][1]),
                          "+f"(acc[mt][nt][2]), "+f"(acc[mt][nt][3])
                        : "r"(a[mt][0]), "r"(a[mt][1]), "r"(a[mt][2]), "r"(a[mt][3]),
                          "r"(b0), "r"(b1));
                }
            }
        }
        __syncthreads();
    }

    // Epilogue: +bias, store h, fused per-column sum/sumsq (per-view)
    float cs0[4] = {}, cs1[4] = {}, cq0[4] = {}, cq1[4] = {};
    #pragma unroll
    for (int nt = 0; nt < 4; nt++) {
        int jc = cn + nt * 8 + tig * 2;
        float bb0 = bias[jc], bb1 = bias[jc + 1];
        #pragma unroll
        for (int mt = 0; mt < 2; mt++) {
            int r0 = m0 + rm + mt * 16 + g;
            int r1 = r0 + 8;
            float h0 = acc[mt][nt][0] + bb0;
            float h1 = acc[mt][nt][1] + bb1;
            float h2 = acc[mt][nt][2] + bb0;
            float h3 = acc[mt][nt][3] + bb1;
            g_h[(size_t)r0 * PD + jc]     = h0;
            g_h[(size_t)r0 * PD + jc + 1] = h1;
            g_h[(size_t)r1 * PD + jc]     = h2;
            g_h[(size_t)r1 * PD + jc + 1] = h3;
            cs0[nt] += h0 + h2;  cs1[nt] += h1 + h3;
            cq0[nt] += h0 * h0 + h2 * h2;
            cq1[nt] += h1 * h1 + h3 * h3;
        }
    }
    int v = m0 >> 12;
    #pragma unroll
    for (int nt = 0; nt < 4; nt++) {
        float a0 = cs0[nt], a1 = cs1[nt], q0 = cq0[nt], q1 = cq1[nt];
        #pragma unroll
        for (int o = 4; o < 32; o <<= 1) {
            a0 += __shfl_xor_sync(0xffffffffu, a0, o);
            a1 += __shfl_xor_sync(0xffffffffu, a1, o);
            q0 += __shfl_xor_sync(0xffffffffu, q0, o);
            q1 += __shfl_xor_sync(0xffffffffu, q1, o);
        }
        if (g == 0) {
            int jc = cn + nt * 8 + tig * 2;
            atomicAdd(&g_sum[v * PD + jc],       a0);
            atomicAdd(&g_sum[v * PD + jc + 1],   a1);
            atomicAdd(&g_sumsq[v * PD + jc],     q0);
            atomicAdd(&g_sumsq[v * PD + jc + 1], q1);
        }
    }
}

// ---------------------------------------------------------------------------
// K2: BN-normalize + cosine row-normalize; emit bf16 (RNE) zn scaled by
// sqrt(EXP_C) so the sim GEMM directly produces the ex2 argument.
// 256 threads = 8 rows x 32 lanes. Also zeroes g_rowsum.
// ---------------------------------------------------------------------------
__global__ __launch_bounds__(256) void k_norm(const float* __restrict__ gamma,
                                              const float* __restrict__ beta) {
    int row  = blockIdx.x * 8 + (threadIdx.x >> 5);
    int lane = threadIdx.x & 31;
    int c    = lane * 4;
    int v    = row >> 12;

    float4 h  = *(const float4*)(g_h + (size_t)row * PD + c);
    float4 su = *(const float4*)(g_sum + v * PD + c);
    float4 sq = *(const float4*)(g_sumsq + v * PD + c);
    float4 gm = *(const float4*)(gamma + c);
    float4 bt = *(const float4*)(beta + c);

    float z[4];
    {
        float mu, var;
        mu = su.x * (1.0f / NV); var = sq.x * (1.0f / NV) - mu * mu;
        z[0] = gm.x * (h.x - mu) * rsqrtf(var + BN_EPS) + bt.x;
        mu = su.y * (1.0f / NV); var = sq.y * (1.0f / NV) - mu * mu;
        z[1] = gm.y * (h.y - mu) * rsqrtf(var + BN_EPS) + bt.y;
        mu = su.z * (1.0f / NV); var = sq.z * (1.0f / NV) - mu * mu;
        z[2] = gm.z * (h.z - mu) * rsqrtf(var + BN_EPS) + bt.z;
        mu = su.w * (1.0f / NV); var = sq.w * (1.0f / NV) - mu * mu;
        z[3] = gm.w * (h.w - mu) * rsqrtf(var + BN_EPS) + bt.w;
    }

    float s2 = z[0] * z[0] + z[1] * z[1] + z[2] * z[2] + z[3] * z[3];
    #pragma unroll
    for (int o = 16; o > 0; o >>= 1)
        s2 += __shfl_xor_sync(0xffffffffu, s2, o);
    float inv = SQRT_EXP_C / fmaxf(sqrtf(s2), COS_EPS);

    __nv_bfloat162 p0 = __floats2bfloat162_rn(z[0] * inv, z[1] * inv);
    __nv_bfloat162 p1 = __floats2bfloat162_rn(z[2] * inv, z[3] * inv);
    uint2 st;
    st.x = *(uint32_t*)&p0;
    st.y = *(uint32_t*)&p1;
    *(uint2*)((char*)g_znb + ((size_t)row * PD + c) * 2) = st;

    if (lane == 0) g_rowsum[row] = 0.0f;
}

// ---------------------------------------------------------------------------
// K3: SYMMETRIC fused sim, bf16 mma + ldmatrix, PAIRED j-tiles per CTA.
// zn pre-scaled -> epilogue is bare ex2(acc). Column sums via 3-step
// reduce-scatter over g-lanes; final owner index for t[j] is 8*j + g.
// ---------------------------------------------------------------------------
#define SPADB 136
#define SROWW (SPADB / 2)                 // 68 words per row
#define TILE_WORDS (128 * SROWW)
#define SIM_SMEM_BYTES (3 * TILE_WORDS * 4)

__device__ __forceinline__ void sim_mainloop(float acc[2][8][4],
                                             uint32_t aAddr, uint32_t bAddr) {
    const uint32_t MT_STRIDE = 16 * SROWW * 4;
    #pragma unroll
    for (int mt = 0; mt < 2; mt++)
        #pragma unroll
        for (int nt = 0; nt < 8; nt++)
            #pragma unroll
            for (int c = 0; c < 4; c++)
                acc[mt][nt][c] = 0.0f;

    #pragma unroll
    for (int ks = 0; ks < 8; ks++) {
        uint32_t kb = (uint32_t)(ks * 32);
        uint32_t a[2][4];
        ldsm_x4(a[0], aAddr + kb);
        ldsm_x4(a[1], aAddr + MT_STRIDE + kb);
        uint32_t b[4][4];
        #pragma unroll
        for (int ntp = 0; ntp < 4; ntp++)
            ldsm_x4(b[ntp], bAddr + ntp * MT_STRIDE + kb);

        #pragma unroll
        for (int ntp = 0; ntp < 4; ntp++) {
            #pragma unroll
            for (int h = 0; h < 2; h++) {
                uint32_t b0 = b[ntp][h];
                uint32_t b1 = b[ntp][h + 2];
                int nt = ntp * 2 + h;
                #pragma unroll
                for (int mt = 0; mt < 2; mt++) {
                    asm volatile(
                        "mma.sync.aligned.m16n8k16.row.col.f32.bf16.bf16.f32 "
                        "{%0,%1,%2,%3}, {%4,%5,%6,%7}, {%8,%9}, {%0,%1,%2,%3};"
                        : "+f"(acc[mt][nt][0]), "+f"(acc[mt][nt][1]),
                          "+f"(acc[mt][nt][2]), "+f"(acc[mt][nt][3])
                        : "r"(a[mt][0]), "r"(a[mt][1]), "r"(a[mt][2]), "r"(a[mt][3]),
                          "r"(b0), "r"(b1));
                }
            }
        }
    }
}

// Per-tile epilogue. Row partials accumulate into rs (deferred); column sums
// (generic/POS tiles) reduced via reduce-scatter and atomically added here.
template <bool DIAG, bool POS>
__device__ __forceinline__ void sim_tile_epi(float acc[2][8][4],
                                             int i0, int j0,
                                             int rm, int cn, int g, int tig,
                                             float rs[2][2]) {
    float cp[16];                         // cp[nt*2+h] column partials
    #pragma unroll
    for (int i = 0; i < 16; i++) cp[i] = 0.0f;

    #pragma unroll
    for (int mt = 0; mt < 2; mt++) {
        int li0 = rm + mt * 16 + g;       // local row
        int li1 = li0 + 8;
        int r0 = i0 + li0, r1 = i0 + li1;
        float s0 = 0.0f, s1 = 0.0f;
        #pragma unroll
        for (int nt = 0; nt < 8; nt++) {
            int lj = cn + nt * 8 + tig * 2;
            float v0 = ex2(acc[mt][nt][0]);
            float v1 = ex2(acc[mt][nt][1]);
            float v2 = ex2(acc[mt][nt][2]);
            float v3 = ex2(acc[mt][nt][3]);
            if (DIAG) {
                if (li0 == lj)     v0 = 0.0f;
                if (li0 == lj + 1) v1 = 0.0f;
                if (li1 == lj)     v2 = 0.0f;
                if (li1 == lj + 1) v3 = 0.0f;
            }
            if (POS) {                    // partner pairs lie on local diagonal
                if (li0 == lj)     { g_pos[r0] = v0; g_pos[j0 + lj]     = v0; }
                if (li0 == lj + 1) { g_pos[r0] = v1; g_pos[j0 + lj + 1] = v1; }
                if (li1 == lj)     { g_pos[r1] = v2; g_pos[j0 + lj]     = v2; }
                if (li1 == lj + 1) { g_pos[r1] = v3; g_pos[j0 + lj + 1] = v3; }
            }
            s0 += v0 + v1;
            s1 += v2 + v3;
            if (!DIAG) { cp[nt * 2] += v0 + v2; cp[nt * 2 + 1] += v1 + v3; }
        }
        rs[mt][0] += s0;
        rs[mt][1] += s1;
    }

    if (!DIAG) {
        // Reduce-scatter over the 8 g-lanes (lane bits 2..4 -> masks 4,8,16).
        // Step1 keeps index 2j+b0; step2 -> 4j+2b1+b0; step3 -> 8j+4b2+2b1+b0
        // = 8j + g. Lane g ends owning cp indices {g, 8+g}, fully summed.
        int b0 = g & 1, b1 = (g >> 1) & 1, b2 = (g >> 2) & 1;
        float w[8];
        #pragma unroll
        for (int j = 0; j < 8; j++) {
            float keep = b0 ? cp[2 * j + 1] : cp[2 * j];
            float send = b0 ? cp[2 * j]     : cp[2 * j + 1];
            w[j] = keep + __shfl_xor_sync(0xffffffffu, send, 4);
        }
        float u[4];
        #pragma unroll
        for (int j = 0; j < 4; j++) {
            float keep = b1 ? w[2 * j + 1] : w[2 * j];
            float send = b1 ? w[2 * j]     : w[2 * j + 1];
            u[j] = keep + __shfl_xor_sync(0xffffffffu, send, 8);
        }
        float t[2];
        #pragma unroll
        for (int j = 0; j < 2; j++) {
            float keep = b2 ? u[2 * j + 1] : u[2 * j];
            float send = b2 ? u[2 * j]     : u[2 * j + 1];
            t[j] = keep + __shfl_xor_sync(0xffffffffu, send, 16);
        }
        #pragma unroll
        for (int j = 0; j < 2; j++) {
            int i = 8 * j + g;            // owner index (NOT bit-reversed)
            atomicAdd(&g_rowsum[j0 + cn + (i >> 1) * 8 + tig * 2 + (i & 1)], t[j]);
        }
    }
}

__global__ __launch_bounds__(256, 2) void k_sim_mma() {
    extern __shared__ uint32_t smw[];
    int tid = threadIdx.x;
    int lane = tid & 31, wid = tid >> 5;

    // decode blockIdx.x -> (bi, pair p); row bi has ceil((NB-bi)/2) pairs
    int T = blockIdx.x, bi = 0;
    for (;;) {
        int np = (NB + 1 - bi) >> 1;
        if (T < np) break;
        T -= np; bi++;
    }
    int bj0 = bi + 2 * T;
    int bj1 = bj0 + 1;
    bool has2 = (bj1 < NB);
    int i0  = bi * 128;
    int j00 = bj0 * 128;
    int j01 = bj1 * 128;

    uint32_t smem0 = (uint32_t)__cvta_generic_to_shared(smw);

    // Load A + B0 (+B1): each tile row = 256 B = 16 uint4; 2048 uint4/tile.
    #pragma unroll
    for (int f = 0; f < 8; f++) {
        int idx = f * 256 + tid;
        int m  = idx >> 4;
        int c4 = idx & 15;
        uint32_t soff = (uint32_t)((m * SROWW + c4 * 4) * 4);
        uint4 va = *(const uint4*)((const char*)g_znb + ((size_t)(i0 + m) * PD) * 2 + c4 * 16);
        *(uint4*)((char*)smw + soff) = va;
        uint4 vb = *(const uint4*)((const char*)g_znb + ((size_t)(j00 + m) * PD) * 2 + c4 * 16);
        *(uint4*)((char*)smw + TILE_WORDS * 4 + soff) = vb;
    }
    if (has2) {
        #pragma unroll
        for (int f = 0; f < 8; f++) {
            int idx = f * 256 + tid;
            int m  = idx >> 4;
            int c4 = idx & 15;
            uint32_t soff = (uint32_t)((m * SROWW + c4 * 4) * 4);
            uint4 vc = *(const uint4*)((const char*)g_znb + ((size_t)(j01 + m) * PD) * 2 + c4 * 16);
            *(uint4*)((char*)smw + 2 * TILE_WORDS * 4 + soff) = vc;
        }
    }
    __syncthreads();

    int g = lane >> 2, tig = lane & 3;
    int rm = (wid & 3) * 32;              // warp row base (i-local)
    int cn = (wid >> 2) * 64;             // warp col base (j-local)

    int frow = ((lane >> 3) & 1) * 8 + (lane & 7);
    int fkw  = ((lane >> 4) & 1) * 4;
    uint32_t aAddr  = smem0 + (uint32_t)(((rm + frow) * SROWW + fkw) * 4);
    uint32_t b0Addr = smem0 + (uint32_t)(TILE_WORDS * 4)
                    + (uint32_t)(((cn + frow) * SROWW + fkw) * 4);
    uint32_t b1Addr = b0Addr + (uint32_t)(TILE_WORDS * 4);

    float acc[2][8][4];
    float rs[2][2] = {};                  // deferred row partial sums

    // Tile 0 (may be DIAG at p==0, or POS at bj0-bi==32)
    sim_mainloop(acc, aAddr, b0Addr);
    if (bj0 == bi)
        sim_tile_epi<true, false>(acc, i0, j00, rm, cn, g, tig, rs);
    else if (bj0 == (bi ^ 32))
        sim_tile_epi<false, true>(acc, i0, j00, rm, cn, g, tig, rs);
    else
        sim_tile_epi<false, false>(acc, i0, j00, rm, cn, g, tig, rs);

    // Tile 1 (always generic: bj1-bi odd, != 0 and != 32)
    if (has2) {
        sim_mainloop(acc, aAddr, b1Addr);
        sim_tile_epi<false, false>(acc, i0, j01, rm, cn, g, tig, rs);
    }

    // Deferred row sums (rows of bi tile; combined over both tiles)
    #pragma unroll
    for (int mt = 0; mt < 2; mt++) {
        float s0 = rs[mt][0], s1 = rs[mt][1];
        s0 += __shfl_xor_sync(0xffffffffu, s0, 1);
        s0 += __shfl_xor_sync(0xffffffffu, s0, 2);
        s1 += __shfl_xor_sync(0xffffffffu, s1, 1);
        s1 += __shfl_xor_sync(0xffffffffu, s1, 2);
        if (tig == 0) {
            int r0 = i0 + rm + mt * 16 + g;
            atomicAdd(&g_rowsum[r0], s0);
            atomicAdd(&g_rowsum[r0 + 8], s1);
        }
    }
}

// ---------------------------------------------------------------------------
// K4: V_i = ln2 * (lg2(rowsum_i) - lg2(pos_i)) via fast MUFU lg2.
// Also re-zeroes BN stat accumulators for the next invocation.
// ---------------------------------------------------------------------------
__global__ void k_final(float* __restrict__ out) {
    int i = blockIdx.x * 256 + threadIdx.x;
    if (i < TWON)
        out[i] = LN2F * (__log2f(g_rowsum[i]) - __log2f(g_pos[i]));
    if (blockIdx.x == 0) {
        g_sum[threadIdx.x]   = 0.0f;      // 256 threads cover 2*PD = 256
        g_sumsq[threadIdx.x] = 0.0f;
    }
}

// ---------------------------------------------------------------------------
extern "C" void kernel_launch(void* const* d_in, const int* in_sizes, int n_in,
                              void* d_out, int out_size) {
    const float* x     = (const float*)d_in[0];
    const float* xt    = (const float*)d_in[1];
    const float* W     = (const float*)d_in[2];
    const float* bias  = (const float*)d_in[3];
    const float* gamma = (const float*)d_in[4];
    const float* beta  = (const float*)d_in[5];
    float* out = (float*)d_out;

    cudaFuncSetAttribute(k_sim_mma, cudaFuncAttributeMaxDynamicSharedMemorySize,
                         SIM_SMEM_BYTES);
    cudaFuncSetAttribute(k_proj_mma, cudaFuncAttributeMaxDynamicSharedMemorySize,
                         PROJ_SMEM);

    // grid = sum over bi of ceil((NB-bi)/2) = 1056
    int n_ctas = 0;
    for (int b = 0; b < NB; b++) n_ctas += (NB + 1 - b) >> 1;

    k_proj_mma<<<TWON / 64, 256, PROJ_SMEM>>>(x, xt, W, bias);
    k_norm <<<TWON / 8, 256>>>(gamma, beta);
    k_sim_mma<<<n_ctas, 256, SIM_SMEM_BYTES>>>();
    k_final<<<32, 256>>>(out);
}